// round 2
// baseline (speedup 1.0000x reference)
#include <cuda_runtime.h>
#include <cstdint>

typedef unsigned long long u64;

// ---------------------------------------------------------------------------
// dilate_block — sparse-conv residual pyramid, round 2:
//   * packed fma.rn.f32x2 (pairs over adjacent input channels)
//   * cp.async double-buffered gather (zfill for missing neighbors)
//   * weights pre-transposed to [K][co][ci] for LDG.128
//   * two-stage deterministic BN reduction
// ---------------------------------------------------------------------------

static constexpr int TILE = 32;            // output rows per block
static constexpr int MAXR = 640000;        // hard bound on row count
static constexpr int MAXBLK = MAXR / TILE + 2;

// scratch (static __device__: allocation-free rule)
__device__ __align__(16) float g_A [MAXR * 64];
__device__ __align__(16) float g_B [MAXR * 64];
__device__ __align__(16) float g_C [MAXR * 64];
__device__ __align__(16) float g_X1[MAXR * 64];
__device__ __align__(16) float g_X2[MAXR * 64];
__device__ __align__(16) float g_X3[MAXR * 64];
__device__ float g_pS[MAXBLK * 64];
__device__ float g_pQ[MAXBLK * 64];
__device__ float g_r1[64 * 128];
__device__ float g_st[4 * 128];            // 4 slots of [mean[64], rstd[64]]
__device__ __align__(16) float g_Wt[528384];

__device__ __forceinline__ u64 ffma2(u64 a, u64 b, u64 c) {
    u64 d;
    asm("fma.rn.f32x2 %0, %1, %2, %3;" : "=l"(d) : "l"(a), "l"(b), "l"(c));
    return d;
}

// ---------------------------------------------------------------------------
// weight transpose: src [K][CIN][64] -> dst [K][64][CIN]
// ---------------------------------------------------------------------------
__global__ void wtrans_kernel(const float* __restrict__ src, float* __restrict__ dst, int CIN)
{
    const int k = blockIdx.x;
    for (int i = threadIdx.x; i < CIN * 64; i += blockDim.x) {
        const int ci = i >> 6;
        const int co = i & 63;
        dst[(size_t)(k * 64 + co) * CIN + ci] = src[(size_t)(k * CIN + ci) * 64 + co];
    }
}

// ---------------------------------------------------------------------------
// Gather-GEMM sparse conv (raw: input already activated if needed).
//   out[n, co] = sum_k sum_ci  in[nbr[k,n], ci] * W[k, ci, co]
// Missing neighbor (index >= nIn) contributes zero (cp.async zfill).
// Emits per-block column partial sums/sumsq (deterministic order).
// ---------------------------------------------------------------------------
template <int CIN, int K>
__global__ void __launch_bounds__(256)
conv_kernel(const float* __restrict__ in, int nIn,
            const int* __restrict__ nbr, int nOut,
            const float* __restrict__ Wt,          // [K][64][CIN]
            float* __restrict__ out,
            float* __restrict__ pSum, float* __restrict__ pSq)
{
    __shared__ __align__(16) float sh[2][TILE][CIN];
    __shared__ float red[2][4][64];

    const int t  = threadIdx.x;
    const int co = t & 63;
    const int rq = t >> 6;                  // 0..3: row quarter (8 rows each)
    const int rowBase = blockIdx.x * TILE;

    const int gr = t >> 3;                  // 0..31 gather row
    const int gl = t & 7;                   // 0..7 gather lane
    const int grow = rowBase + gr;

    auto prefetch = [&](int k) {
        int j = nIn;
        if (grow < nOut) j = nbr[(size_t)k * nOut + grow];
        const bool v = (j < nIn);
        const float* src = in + (size_t)(v ? j : 0) * CIN + gl * 4;
        uint32_t dst = (uint32_t)__cvta_generic_to_shared(&sh[k & 1][gr][gl * 4]);
        const int sz = v ? 16 : 0;
        asm volatile("cp.async.ca.shared.global [%0], [%1], 16, %2;\n"
                     :: "r"(dst), "l"(src), "r"(sz));
        if (CIN == 64) {
            asm volatile("cp.async.ca.shared.global [%0], [%1], 16, %2;\n"
                         :: "r"(dst + 128), "l"(src + 32), "r"(sz));
        }
    };

    u64 acc2[8];
#pragma unroll
    for (int r = 0; r < 8; ++r) acc2[r] = 0ull;

    const float* wrow = Wt + (size_t)co * CIN;

    prefetch(0);
    asm volatile("cp.async.commit_group;\n");

    for (int k = 0; k < K; ++k) {
        if (k + 1 < K) {
            prefetch(k + 1);
            asm volatile("cp.async.commit_group;\n");
            asm volatile("cp.async.wait_group 1;\n");
        } else {
            asm volatile("cp.async.wait_group 0;\n");
        }
        __syncthreads();

        const float* wk = wrow + (size_t)k * (CIN * 64);
        const float* srow = &sh[k & 1][rq * 8][0];
#pragma unroll
        for (int ci = 0; ci < CIN; ci += 4) {
            const ulonglong2 w2 = *reinterpret_cast<const ulonglong2*>(wk + ci);
#pragma unroll
            for (int r = 0; r < 8; ++r) {
                const ulonglong2 s2 =
                    *reinterpret_cast<const ulonglong2*>(srow + r * CIN + ci);
                acc2[r] = ffma2(s2.x, w2.x, acc2[r]);
                acc2[r] = ffma2(s2.y, w2.y, acc2[r]);
            }
        }
        __syncthreads();
    }

    float s = 0.f, q = 0.f;
#pragma unroll
    for (int r = 0; r < 8; ++r) {
        const int orow = rowBase + rq * 8 + r;
        const float lo = __uint_as_float((unsigned)acc2[r]);
        const float hi = __uint_as_float((unsigned)(acc2[r] >> 32));
        const float v = lo + hi;
        if (orow < nOut) {
            out[(size_t)orow * 64 + co] = v;
            s += v;
            q += v * v;
        }
    }
    if (pSum != nullptr) {
        red[0][rq][co] = s;
        red[1][rq][co] = q;
        __syncthreads();
        if (rq == 0) {
            pSum[(size_t)blockIdx.x * 64 + co] =
                (red[0][0][co] + red[0][1][co]) + (red[0][2][co] + red[0][3][co]);
            pSq[(size_t)blockIdx.x * 64 + co] =
                (red[1][0][co] + red[1][1][co]) + (red[1][2][co] + red[1][3][co]);
        }
    }
}

// ---------------------------------------------------------------------------
// BN stats, two-stage deterministic reduction
// ---------------------------------------------------------------------------
__global__ void __launch_bounds__(256)
bn_stage1(const float* __restrict__ pS, const float* __restrict__ pQ,
          int nB, float* __restrict__ r1)
{
    __shared__ float sh[2][4][64];
    const int t = threadIdx.x;
    const int co = t & 63;
    const int sub = t >> 6;
    float s = 0.f, q = 0.f;
    for (int b = blockIdx.x * 4 + sub; b < nB; b += 64 * 4) {
        s += pS[(size_t)b * 64 + co];
        q += pQ[(size_t)b * 64 + co];
    }
    sh[0][sub][co] = s;
    sh[1][sub][co] = q;
    __syncthreads();
    if (sub == 0) {
        r1[blockIdx.x * 128 + co] =
            (sh[0][0][co] + sh[0][1][co]) + (sh[0][2][co] + sh[0][3][co]);
        r1[blockIdx.x * 128 + 64 + co] =
            (sh[1][0][co] + sh[1][1][co]) + (sh[1][2][co] + sh[1][3][co]);
    }
}

__global__ void bn_stage2(const float* __restrict__ r1, int nRows, float* __restrict__ st)
{
    const int t = threadIdx.x;   // 64 threads
    float s = 0.f, q = 0.f;
#pragma unroll 8
    for (int b = 0; b < 64; ++b) {
        s += r1[b * 128 + t];
        q += r1[b * 128 + 64 + t];
    }
    const float inv = 1.0f / (float)nRows;
    const float m = s * inv;
    const float var = q * inv - m * m;
    st[t] = m;
    st[64 + t] = rsqrtf(var + 1e-5f);
}

// ---------------------------------------------------------------------------
// x = lrelu(bn(x)) in place (float4)
// ---------------------------------------------------------------------------
__global__ void bnact_kernel(float4* __restrict__ x, const float* __restrict__ st, long long n4)
{
    const long long i = (long long)blockIdx.x * blockDim.x + threadIdx.x;
    if (i >= n4) return;
    const int c = ((int)(i & 15)) * 4;
    float4 v = x[i];
    v.x = (v.x - st[c + 0]) * st[64 + c + 0];
    v.y = (v.y - st[c + 1]) * st[64 + c + 1];
    v.z = (v.z - st[c + 2]) * st[64 + c + 2];
    v.w = (v.w - st[c + 3]) * st[64 + c + 3];
    v.x = v.x > 0.f ? v.x : 0.01f * v.x;
    v.y = v.y > 0.f ? v.y : 0.01f * v.y;
    v.z = v.z > 0.f ? v.z : 0.01f * v.z;
    v.w = v.w > 0.f ? v.w : 0.01f * v.w;
    x[i] = v;
}

// ---------------------------------------------------------------------------
// x = lrelu(bn(a)) + lrelu(bn(b))  (residual merge, float4)
// ---------------------------------------------------------------------------
__global__ void combine_kernel(const float4* __restrict__ a, const float* __restrict__ sa,
                               const float4* __restrict__ b, const float* __restrict__ sb,
                               float4* __restrict__ o, long long n4)
{
    const long long i = (long long)blockIdx.x * blockDim.x + threadIdx.x;
    if (i >= n4) return;
    const int c = ((int)(i & 15)) * 4;
    float4 va = a[i];
    float4 vb = b[i];
    float4 r;
    float x;
    x = (va.x - sa[c + 0]) * sa[64 + c + 0]; x = x > 0.f ? x : 0.01f * x; r.x = x;
    x = (va.y - sa[c + 1]) * sa[64 + c + 1]; x = x > 0.f ? x : 0.01f * x; r.y = x;
    x = (va.z - sa[c + 2]) * sa[64 + c + 2]; x = x > 0.f ? x : 0.01f * x; r.z = x;
    x = (va.w - sa[c + 3]) * sa[64 + c + 3]; x = x > 0.f ? x : 0.01f * x; r.w = x;
    x = (vb.x - sb[c + 0]) * sb[64 + c + 0]; x = x > 0.f ? x : 0.01f * x; r.x += x;
    x = (vb.y - sb[c + 1]) * sb[64 + c + 1]; x = x > 0.f ? x : 0.01f * x; r.y += x;
    x = (vb.z - sb[c + 2]) * sb[64 + c + 2]; x = x > 0.f ? x : 0.01f * x; r.z += x;
    x = (vb.w - sb[c + 3]) * sb[64 + c + 3]; x = x > 0.f ? x : 0.01f * x; r.w += x;
    o[i] = r;
}

// ---------------------------------------------------------------------------
// out[m] = [x1 | x2 | x3] @ down_w  (Wt: [3][64][64] transposed)
// ---------------------------------------------------------------------------
__global__ void __launch_bounds__(256)
final_kernel(const float* __restrict__ X1, const float* __restrict__ X2,
             const float* __restrict__ X3, const float* __restrict__ Wt,
             float* __restrict__ out, int M)
{
    __shared__ __align__(16) float sh[TILE][64];
    const int t = threadIdx.x;
    const int co = t & 63;
    const int rq = t >> 6;
    const int rowBase = blockIdx.x * TILE;

    u64 acc2[8];
#pragma unroll
    for (int r = 0; r < 8; ++r) acc2[r] = 0ull;

    const float* srcs[3] = {X1, X2, X3};
    for (int s = 0; s < 3; ++s) {
        __syncthreads();
        const float* src = srcs[s];
#pragma unroll
        for (int i = t; i < TILE * 16; i += 256) {
            const int r = i >> 4;
            const int c4 = (i & 15) * 4;
            const int orow = rowBase + r;
            float4 v = make_float4(0.f, 0.f, 0.f, 0.f);
            if (orow < M) v = *reinterpret_cast<const float4*>(src + (size_t)orow * 64 + c4);
            *reinterpret_cast<float4*>(&sh[r][c4]) = v;
        }
        __syncthreads();
        const float* wk = Wt + s * 64 * 64 + co * 64;
#pragma unroll
        for (int ci = 0; ci < 64; ci += 4) {
            const ulonglong2 w2 = *reinterpret_cast<const ulonglong2*>(wk + ci);
#pragma unroll
            for (int r = 0; r < 8; ++r) {
                const ulonglong2 s2 = *reinterpret_cast<const ulonglong2*>(&sh[rq * 8 + r][ci]);
                acc2[r] = ffma2(s2.x, w2.x, acc2[r]);
                acc2[r] = ffma2(s2.y, w2.y, acc2[r]);
            }
        }
    }
#pragma unroll
    for (int r = 0; r < 8; ++r) {
        const int orow = rowBase + rq * 8 + r;
        if (orow < M) {
            const float lo = __uint_as_float((unsigned)acc2[r]);
            const float hi = __uint_as_float((unsigned)(acc2[r] >> 32));
            out[(size_t)orow * 64 + co] = lo + hi;
        }
    }
}

// ---------------------------------------------------------------------------
extern "C" void kernel_launch(void* const* d_in, const int* in_sizes, int n_in,
                              void* d_out, int out_size)
{
    const float* feats   = (const float*)d_in[0];
    const float* b1_w1   = (const float*)d_in[1];
    const float* b1_w1_2 = (const float*)d_in[2];
    const float* b1_w2   = (const float*)d_in[3];
    const float* b1_w2_2 = (const float*)d_in[4];
    const float* pool_w  = (const float*)d_in[5];
    const float* b2_w1   = (const float*)d_in[6];
    const float* b2_w1_2 = (const float*)d_in[7];
    const float* b2_w2   = (const float*)d_in[8];
    const float* b2_w2_2 = (const float*)d_in[9];
    const float* b3_w1   = (const float*)d_in[10];
    const float* b3_w1_2 = (const float*)d_in[11];
    const float* b3_w2   = (const float*)d_in[12];
    const float* b3_w2_2 = (const float*)d_in[13];
    const float* down_w  = (const float*)d_in[14];
    const int* n331_1 = (const int*)d_in[15];
    const int* n313_1 = (const int*)d_in[16];
    const int* pool_n = (const int*)d_in[17];
    const int* n331_2 = (const int*)d_in[18];
    const int* n313_2 = (const int*)d_in[19];
    const int* n331_3 = (const int*)d_in[20];
    const int* n313_3 = (const int*)d_in[21];

    const int N = in_sizes[0] / 32;
    const int M = out_size / 64;

    float *A, *B, *C, *X1, *X2, *X3, *pS, *pQ, *r1, *st, *Wt;
    cudaGetSymbolAddress((void**)&A,  g_A);
    cudaGetSymbolAddress((void**)&B,  g_B);
    cudaGetSymbolAddress((void**)&C,  g_C);
    cudaGetSymbolAddress((void**)&X1, g_X1);
    cudaGetSymbolAddress((void**)&X2, g_X2);
    cudaGetSymbolAddress((void**)&X3, g_X3);
    cudaGetSymbolAddress((void**)&pS, g_pS);
    cudaGetSymbolAddress((void**)&pQ, g_pQ);
    cudaGetSymbolAddress((void**)&r1, g_r1);
    cudaGetSymbolAddress((void**)&st, g_st);
    cudaGetSymbolAddress((void**)&Wt, g_Wt);
    float* st0 = st;
    float* st1 = st + 128;
    float* st2 = st + 256;
    float* st3 = st + 384;

    // transposed weight offsets in g_Wt (floats)
    const size_t o0 = 0;        // b1_w1   (9,32)
    const size_t o1 = 18432;    // b1_w1_2 (9,64)
    const size_t o2 = 55296;    // b1_w2   (9,32)
    const size_t o3 = 73728;    // b1_w2_2 (9,64)
    const size_t o4 = 110592;   // pool    (27,64)
    const size_t o5 = 221184;   // b2_w1
    const size_t o6 = 258048;   // b2_w1_2
    const size_t o7 = 294912;   // b2_w2
    const size_t o8 = 331776;   // b2_w2_2
    const size_t o9 = 368640;   // b3_w1
    const size_t o10 = 405504;  // b3_w1_2
    const size_t o11 = 442368;  // b3_w2
    const size_t o12 = 479232;  // b3_w2_2
    const size_t o13 = 516096;  // down    (3,64)

    wtrans_kernel<<<9, 256>>>(b1_w1,   Wt + o0,  32);
    wtrans_kernel<<<9, 256>>>(b1_w1_2, Wt + o1,  64);
    wtrans_kernel<<<9, 256>>>(b1_w2,   Wt + o2,  32);
    wtrans_kernel<<<9, 256>>>(b1_w2_2, Wt + o3,  64);
    wtrans_kernel<<<27, 256>>>(pool_w, Wt + o4,  64);
    wtrans_kernel<<<9, 256>>>(b2_w1,   Wt + o5,  64);
    wtrans_kernel<<<9, 256>>>(b2_w1_2, Wt + o6,  64);
    wtrans_kernel<<<9, 256>>>(b2_w2,   Wt + o7,  64);
    wtrans_kernel<<<9, 256>>>(b2_w2_2, Wt + o8,  64);
    wtrans_kernel<<<9, 256>>>(b3_w1,   Wt + o9,  64);
    wtrans_kernel<<<9, 256>>>(b3_w1_2, Wt + o10, 64);
    wtrans_kernel<<<9, 256>>>(b3_w2,   Wt + o11, 64);
    wtrans_kernel<<<9, 256>>>(b3_w2_2, Wt + o12, 64);
    wtrans_kernel<<<3, 256>>>(down_w,  Wt + o13, 64);

    const int gN = (N + TILE - 1) / TILE;
    const int gM = (M + TILE - 1) / TILE;
    const long long n4N = (long long)N * 16;
    const long long n4M = (long long)M * 16;
    const int gbN = (int)((n4N + 255) / 256);
    const int gbM = (int)((n4M + 255) / 256);

    // ---- block 1 (N rows, 32 -> 64) ----
    conv_kernel<32, 9><<<gN, 256>>>(feats, N, n331_1, N, Wt + o0, A, pS, pQ);
    bn_stage1<<<64, 256>>>(pS, pQ, gN, r1);
    bn_stage2<<<1, 64>>>(r1, N, st0);
    bnact_kernel<<<gbN, 256>>>((float4*)A, st0, n4N);
    conv_kernel<64, 9><<<gN, 256>>>(A, N, n313_1, N, Wt + o1, B, pS, pQ);
    bn_stage1<<<64, 256>>>(pS, pQ, gN, r1);
    bn_stage2<<<1, 64>>>(r1, N, st1);
    conv_kernel<32, 9><<<gN, 256>>>(feats, N, n313_1, N, Wt + o2, C, pS, pQ);
    bn_stage1<<<64, 256>>>(pS, pQ, gN, r1);
    bn_stage2<<<1, 64>>>(r1, N, st2);
    bnact_kernel<<<gbN, 256>>>((float4*)C, st2, n4N);
    conv_kernel<64, 9><<<gN, 256>>>(C, N, n331_1, N, Wt + o3, A, pS, pQ);
    bn_stage1<<<64, 256>>>(pS, pQ, gN, r1);
    bn_stage2<<<1, 64>>>(r1, N, st3);
    combine_kernel<<<gbN, 256>>>((const float4*)A, st3, (const float4*)B, st1,
                                 (float4*)C, n4N);

    // ---- pool (strided SparseConv3d, K=27): C (N rows) -> X1 (M rows) ----
    conv_kernel<64, 27><<<gM, 256>>>(C, N, pool_n, M, Wt + o4, X1, nullptr, nullptr);

    // ---- block 2 (M rows, dilation 2) ----
    conv_kernel<64, 9><<<gM, 256>>>(X1, M, n331_2, M, Wt + o5, A, pS, pQ);
    bn_stage1<<<64, 256>>>(pS, pQ, gM, r1);
    bn_stage2<<<1, 64>>>(r1, M, st0);
    bnact_kernel<<<gbM, 256>>>((float4*)A, st0, n4M);
    conv_kernel<64, 9><<<gM, 256>>>(A, M, n313_2, M, Wt + o6, B, pS, pQ);
    bn_stage1<<<64, 256>>>(pS, pQ, gM, r1);
    bn_stage2<<<1, 64>>>(r1, M, st1);
    conv_kernel<64, 9><<<gM, 256>>>(X1, M, n313_2, M, Wt + o7, C, pS, pQ);
    bn_stage1<<<64, 256>>>(pS, pQ, gM, r1);
    bn_stage2<<<1, 64>>>(r1, M, st2);
    bnact_kernel<<<gbM, 256>>>((float4*)C, st2, n4M);
    conv_kernel<64, 9><<<gM, 256>>>(C, M, n331_2, M, Wt + o8, A, pS, pQ);
    bn_stage1<<<64, 256>>>(pS, pQ, gM, r1);
    bn_stage2<<<1, 64>>>(r1, M, st3);
    combine_kernel<<<gbM, 256>>>((const float4*)A, st3, (const float4*)B, st1,
                                 (float4*)X2, n4M);

    // ---- block 3 (M rows, dilation 3) ----
    conv_kernel<64, 9><<<gM, 256>>>(X2, M, n331_3, M, Wt + o9, A, pS, pQ);
    bn_stage1<<<64, 256>>>(pS, pQ, gM, r1);
    bn_stage2<<<1, 64>>>(r1, M, st0);
    bnact_kernel<<<gbM, 256>>>((float4*)A, st0, n4M);
    conv_kernel<64, 9><<<gM, 256>>>(A, M, n313_3, M, Wt + o10, B, pS, pQ);
    bn_stage1<<<64, 256>>>(pS, pQ, gM, r1);
    bn_stage2<<<1, 64>>>(r1, M, st1);
    conv_kernel<64, 9><<<gM, 256>>>(X2, M, n313_3, M, Wt + o11, C, pS, pQ);
    bn_stage1<<<64, 256>>>(pS, pQ, gM, r1);
    bn_stage2<<<1, 64>>>(r1, M, st2);
    bnact_kernel<<<gbM, 256>>>((float4*)C, st2, n4M);
    conv_kernel<64, 9><<<gM, 256>>>(C, M, n331_3, M, Wt + o12, A, pS, pQ);
    bn_stage1<<<64, 256>>>(pS, pQ, gM, r1);
    bn_stage2<<<1, 64>>>(r1, M, st3);
    combine_kernel<<<gbM, 256>>>((const float4*)A, st3, (const float4*)B, st1,
                                 (float4*)X3, n4M);

    // ---- final 1x1 fuse ----
    final_kernel<<<gM, 256>>>(X1, X2, X3, Wt + o13, (float*)d_out, M);
}

// round 3
// speedup vs baseline: 2.2463x; 2.2463x over previous
#include <cuda_runtime.h>
#include <cstdint>

typedef unsigned long long u64;

// ---------------------------------------------------------------------------
// dilate_block — sparse-conv residual pyramid, round 3:
//   * fma.rn.f32x2 packed over adjacent input channels
//   * weights packed [K][CIN/4][co][4]  (coalesced LDG.128, pairs ready)
//   * register-staged double-buffered gather (1 syncthreads per tap)
//   * two-stage deterministic BN reduction, single fused weight-transpose
// ---------------------------------------------------------------------------

static constexpr int TILE = 16;            // output rows per block
static constexpr int MAXR = 640000;        // hard bound on row count
static constexpr int MAXBLK = MAXR / TILE + 2;

// scratch (static __device__: allocation-free rule)
__device__ __align__(16) float g_A [MAXR * 64];
__device__ __align__(16) float g_B [MAXR * 64];
__device__ __align__(16) float g_C [MAXR * 64];
__device__ __align__(16) float g_X1[MAXR * 64];
__device__ __align__(16) float g_X2[MAXR * 64];
__device__ __align__(16) float g_X3[MAXR * 64];
__device__ float g_pS[MAXBLK * 64];
__device__ float g_pQ[MAXBLK * 64];
__device__ float g_r1[64 * 128];
__device__ float g_st[4 * 128];            // 4 slots of [mean[64], rstd[64]]
__device__ __align__(16) float g_Wt[528384];

__device__ __forceinline__ u64 ffma2(u64 a, u64 b, u64 c) {
    u64 d;
    asm("fma.rn.f32x2 %0, %1, %2, %3;" : "=l"(d) : "l"(a), "l"(b), "l"(c));
    return d;
}

// ---------------------------------------------------------------------------
// fused weight transpose+pack: src [K][CIN][64] -> dst [K][CIN/4][64][4]
//   dst[((k*CIN/4 + q)*64 + co)*4 + j] = src[(k*CIN + 4q + j)*64 + co]
// one launch handles all 14 weight tensors; blockIdx maps to (tensor, k)
// ---------------------------------------------------------------------------
struct WPtrs { const float* p[14]; };

__global__ void __launch_bounds__(256)
wtrans_all(WPtrs w, float* __restrict__ dst)
{
    const int Ks[14]   = {9,9,9,9,27,9,9,9,9,9,9,9,9,3};
    const int CINs[14] = {32,64,32,64,64,64,64,64,64,64,64,64,64,64};
    const int offs[14] = {0,18432,55296,73728,110592,221184,258048,294912,
                          331776,368640,405504,442368,479232,516096};
    int b = blockIdx.x, i = 0;
    while (b >= Ks[i]) { b -= Ks[i]; ++i; }
    const int CIN = CINs[i];
    const float* src = w.p[i] + (size_t)b * CIN * 64;
    float* d = dst + offs[i] + (size_t)b * CIN * 64;
    for (int e = threadIdx.x; e < CIN * 64; e += 256) {
        const int ci = e >> 6, co = e & 63;
        const int q = ci >> 2, j = ci & 3;
        d[(q * 64 + co) * 4 + j] = src[e];
    }
}

// ---------------------------------------------------------------------------
// Gather-GEMM sparse conv.
//   out[n, co] = sum_k sum_ci  in[nbr[k,n], ci] * W[k, ci, co]
// Missing neighbor (index >= nIn) contributes zero.
// Register-staged double buffer: prefetch tap k+1 into regs while computing
// tap k; one __syncthreads per tap. Weights packed [K][CIN/4][64][4].
// Emits per-block column partial sums/sumsq (deterministic order).
// ---------------------------------------------------------------------------
template <int CIN, int K>
__global__ void __launch_bounds__(128)
conv_kernel(const float* __restrict__ in, int nIn,
            const int* __restrict__ nbr, int nOut,
            const float* __restrict__ Wp,
            float* __restrict__ out,
            float* __restrict__ pSum, float* __restrict__ pSq)
{
    __shared__ __align__(16) float sh[2][TILE][CIN];
    __shared__ float red[2][2][64];

    const int t  = threadIdx.x;
    const int co = t & 63;
    const int rh = t >> 6;                  // 0/1: row half (8 rows each)
    const int rowBase = blockIdx.x * TILE;

    const int gr = t >> 3;                  // 0..15 gather row
    const int gl = t & 7;                   // 0..7 gather lane
    const int grow = rowBase + gr;
    const bool rowOK = (grow < nOut);

    float4 pv0, pv1;
    auto prefetch = [&](int k) {
        int j = rowOK ? nbr[(size_t)k * nOut + grow] : nIn;
        if (j < nIn) {
            const float4* s = reinterpret_cast<const float4*>(in + (size_t)j * CIN);
            pv0 = s[gl];
            if (CIN == 64) pv1 = s[gl + 8];
        } else {
            pv0 = make_float4(0.f, 0.f, 0.f, 0.f);
            if (CIN == 64) pv1 = pv0;
        }
    };
    auto sts = [&](int buf) {
        *reinterpret_cast<float4*>(&sh[buf][gr][gl * 4]) = pv0;
        if (CIN == 64) *reinterpret_cast<float4*>(&sh[buf][gr][gl * 4 + 32]) = pv1;
    };

    u64 acc2[8];
#pragma unroll
    for (int r = 0; r < 8; ++r) acc2[r] = 0ull;

    prefetch(0);
    sts(0);

    for (int k = 0; k < K; ++k) {
        __syncthreads();
        if (k + 1 < K) prefetch(k + 1);     // LDGs overlap the FMA burst below

        const float* wkp = Wp + (size_t)k * (CIN * 64);
        const float* srow = &sh[k & 1][rh * 8][0];
#pragma unroll
        for (int q = 0; q < CIN / 4; ++q) {
            const ulonglong2 w2 =
                *reinterpret_cast<const ulonglong2*>(wkp + (q * 64 + co) * 4);
#pragma unroll
            for (int r = 0; r < 8; ++r) {
                const ulonglong2 s2 =
                    *reinterpret_cast<const ulonglong2*>(srow + r * CIN + q * 4);
                acc2[r] = ffma2(s2.x, w2.x, acc2[r]);
                acc2[r] = ffma2(s2.y, w2.y, acc2[r]);
            }
        }
        if (k + 1 < K) sts((k + 1) & 1);
    }

    float s = 0.f, q = 0.f;
#pragma unroll
    for (int r = 0; r < 8; ++r) {
        const int orow = rowBase + rh * 8 + r;
        const float lo = __uint_as_float((unsigned)acc2[r]);
        const float hi = __uint_as_float((unsigned)(acc2[r] >> 32));
        const float v = lo + hi;
        if (orow < nOut) {
            out[(size_t)orow * 64 + co] = v;
            s += v;
            q += v * v;
        }
    }
    if (pSum != nullptr) {
        red[0][rh][co] = s;
        red[1][rh][co] = q;
        __syncthreads();
        if (rh == 0) {
            pSum[(size_t)blockIdx.x * 64 + co] = red[0][0][co] + red[0][1][co];
            pSq [(size_t)blockIdx.x * 64 + co] = red[1][0][co] + red[1][1][co];
        }
    }
}

// ---------------------------------------------------------------------------
// BN stats, two-stage deterministic reduction
// ---------------------------------------------------------------------------
__global__ void __launch_bounds__(256)
bn_stage1(const float* __restrict__ pS, const float* __restrict__ pQ,
          int nB, float* __restrict__ r1)
{
    __shared__ float sh[2][4][64];
    const int t = threadIdx.x;
    const int co = t & 63;
    const int sub = t >> 6;
    float s = 0.f, q = 0.f;
    for (int b = blockIdx.x * 4 + sub; b < nB; b += 64 * 4) {
        s += pS[(size_t)b * 64 + co];
        q += pQ[(size_t)b * 64 + co];
    }
    sh[0][sub][co] = s;
    sh[1][sub][co] = q;
    __syncthreads();
    if (sub == 0) {
        r1[blockIdx.x * 128 + co] =
            (sh[0][0][co] + sh[0][1][co]) + (sh[0][2][co] + sh[0][3][co]);
        r1[blockIdx.x * 128 + 64 + co] =
            (sh[1][0][co] + sh[1][1][co]) + (sh[1][2][co] + sh[1][3][co]);
    }
}

__global__ void bn_stage2(const float* __restrict__ r1, int nRows, float* __restrict__ st)
{
    const int t = threadIdx.x;   // 64 threads
    float s = 0.f, q = 0.f;
#pragma unroll 8
    for (int b = 0; b < 64; ++b) {
        s += r1[b * 128 + t];
        q += r1[b * 128 + 64 + t];
    }
    const float inv = 1.0f / (float)nRows;
    const float m = s * inv;
    const float var = q * inv - m * m;
    st[t] = m;
    st[64 + t] = rsqrtf(var + 1e-5f);
}

// ---------------------------------------------------------------------------
// x = lrelu(bn(x)) in place (float4)
// ---------------------------------------------------------------------------
__global__ void bnact_kernel(float4* __restrict__ x, const float* __restrict__ st, long long n4)
{
    const long long i = (long long)blockIdx.x * blockDim.x + threadIdx.x;
    if (i >= n4) return;
    const int c = ((int)(i & 15)) * 4;
    float4 v = x[i];
    v.x = (v.x - st[c + 0]) * st[64 + c + 0];
    v.y = (v.y - st[c + 1]) * st[64 + c + 1];
    v.z = (v.z - st[c + 2]) * st[64 + c + 2];
    v.w = (v.w - st[c + 3]) * st[64 + c + 3];
    v.x = v.x > 0.f ? v.x : 0.01f * v.x;
    v.y = v.y > 0.f ? v.y : 0.01f * v.y;
    v.z = v.z > 0.f ? v.z : 0.01f * v.z;
    v.w = v.w > 0.f ? v.w : 0.01f * v.w;
    x[i] = v;
}

// ---------------------------------------------------------------------------
// x = lrelu(bn(a)) + lrelu(bn(b))  (residual merge, float4)
// ---------------------------------------------------------------------------
__global__ void combine_kernel(const float4* __restrict__ a, const float* __restrict__ sa,
                               const float4* __restrict__ b, const float* __restrict__ sb,
                               float4* __restrict__ o, long long n4)
{
    const long long i = (long long)blockIdx.x * blockDim.x + threadIdx.x;
    if (i >= n4) return;
    const int c = ((int)(i & 15)) * 4;
    float4 va = a[i];
    float4 vb = b[i];
    float4 r;
    float x;
    x = (va.x - sa[c + 0]) * sa[64 + c + 0]; x = x > 0.f ? x : 0.01f * x; r.x = x;
    x = (va.y - sa[c + 1]) * sa[64 + c + 1]; x = x > 0.f ? x : 0.01f * x; r.y = x;
    x = (va.z - sa[c + 2]) * sa[64 + c + 2]; x = x > 0.f ? x : 0.01f * x; r.z = x;
    x = (va.w - sa[c + 3]) * sa[64 + c + 3]; x = x > 0.f ? x : 0.01f * x; r.w = x;
    x = (vb.x - sb[c + 0]) * sb[64 + c + 0]; x = x > 0.f ? x : 0.01f * x; r.x += x;
    x = (vb.y - sb[c + 1]) * sb[64 + c + 1]; x = x > 0.f ? x : 0.01f * x; r.y += x;
    x = (vb.z - sb[c + 2]) * sb[64 + c + 2]; x = x > 0.f ? x : 0.01f * x; r.z += x;
    x = (vb.w - sb[c + 3]) * sb[64 + c + 3]; x = x > 0.f ? x : 0.01f * x; r.w += x;
    o[i] = r;
}

// ---------------------------------------------------------------------------
// out[m] = [x1 | x2 | x3] @ down_w   (Wp: packed [3][16][64][4])
// ---------------------------------------------------------------------------
__global__ void __launch_bounds__(128)
final_kernel(const float* __restrict__ X1, const float* __restrict__ X2,
             const float* __restrict__ X3, const float* __restrict__ Wp,
             float* __restrict__ out, int M)
{
    __shared__ __align__(16) float sh[TILE][64];
    const int t = threadIdx.x;
    const int co = t & 63;
    const int rh = t >> 6;
    const int rowBase = blockIdx.x * TILE;
    const int gr = t >> 3;
    const int gl = t & 7;
    const int grow = rowBase + gr;

    u64 acc2[8];
#pragma unroll
    for (int r = 0; r < 8; ++r) acc2[r] = 0ull;

    const float* srcs[3] = {X1, X2, X3};
    for (int s = 0; s < 3; ++s) {
        __syncthreads();
        float4 v0 = make_float4(0.f, 0.f, 0.f, 0.f), v1 = v0;
        if (grow < M) {
            const float4* sp = reinterpret_cast<const float4*>(srcs[s] + (size_t)grow * 64);
            v0 = sp[gl];
            v1 = sp[gl + 8];
        }
        *reinterpret_cast<float4*>(&sh[gr][gl * 4]) = v0;
        *reinterpret_cast<float4*>(&sh[gr][gl * 4 + 32]) = v1;
        __syncthreads();

        const float* wkp = Wp + (size_t)s * (64 * 64);
#pragma unroll
        for (int q = 0; q < 16; ++q) {
            const ulonglong2 w2 =
                *reinterpret_cast<const ulonglong2*>(wkp + (q * 64 + co) * 4);
#pragma unroll
            for (int r = 0; r < 8; ++r) {
                const ulonglong2 s2 =
                    *reinterpret_cast<const ulonglong2*>(&sh[rh * 8 + r][q * 4]);
                acc2[r] = ffma2(s2.x, w2.x, acc2[r]);
                acc2[r] = ffma2(s2.y, w2.y, acc2[r]);
            }
        }
    }
#pragma unroll
    for (int r = 0; r < 8; ++r) {
        const int orow = rowBase + rh * 8 + r;
        if (orow < M) {
            const float lo = __uint_as_float((unsigned)acc2[r]);
            const float hi = __uint_as_float((unsigned)(acc2[r] >> 32));
            out[(size_t)orow * 64 + co] = lo + hi;
        }
    }
}

// ---------------------------------------------------------------------------
extern "C" void kernel_launch(void* const* d_in, const int* in_sizes, int n_in,
                              void* d_out, int out_size)
{
    const float* feats = (const float*)d_in[0];
    const int* n331_1 = (const int*)d_in[15];
    const int* n313_1 = (const int*)d_in[16];
    const int* pool_n = (const int*)d_in[17];
    const int* n331_2 = (const int*)d_in[18];
    const int* n313_2 = (const int*)d_in[19];
    const int* n331_3 = (const int*)d_in[20];
    const int* n313_3 = (const int*)d_in[21];

    const int N = in_sizes[0] / 32;
    const int M = out_size / 64;

    float *A, *B, *C, *X1, *X2, *X3, *pS, *pQ, *r1, *st, *Wt;
    cudaGetSymbolAddress((void**)&A,  g_A);
    cudaGetSymbolAddress((void**)&B,  g_B);
    cudaGetSymbolAddress((void**)&C,  g_C);
    cudaGetSymbolAddress((void**)&X1, g_X1);
    cudaGetSymbolAddress((void**)&X2, g_X2);
    cudaGetSymbolAddress((void**)&X3, g_X3);
    cudaGetSymbolAddress((void**)&pS, g_pS);
    cudaGetSymbolAddress((void**)&pQ, g_pQ);
    cudaGetSymbolAddress((void**)&r1, g_r1);
    cudaGetSymbolAddress((void**)&st, g_st);
    cudaGetSymbolAddress((void**)&Wt, g_Wt);
    float* st0 = st;
    float* st1 = st + 128;
    float* st2 = st + 256;
    float* st3 = st + 384;

    // packed weight offsets in g_Wt (floats)
    const size_t o0 = 0;        // b1_w1   (9,32)
    const size_t o1 = 18432;    // b1_w1_2 (9,64)
    const size_t o2 = 55296;    // b1_w2   (9,32)
    const size_t o3 = 73728;    // b1_w2_2 (9,64)
    const size_t o4 = 110592;   // pool    (27,64)
    const size_t o5 = 221184;   // b2_w1
    const size_t o6 = 258048;   // b2_w1_2
    const size_t o7 = 294912;   // b2_w2
    const size_t o8 = 331776;   // b2_w2_2
    const size_t o9 = 368640;   // b3_w1
    const size_t o10 = 405504;  // b3_w1_2
    const size_t o11 = 442368;  // b3_w2
    const size_t o12 = 479232;  // b3_w2_2
    const size_t o13 = 516096;  // down    (3,64)

    WPtrs wp;
    for (int i = 0; i < 14; ++i) wp.p[i] = (const float*)d_in[1 + i];
    wtrans_all<<<138, 256>>>(wp, Wt);

    const int gN = (N + TILE - 1) / TILE;
    const int gM = (M + TILE - 1) / TILE;
    const long long n4N = (long long)N * 16;
    const long long n4M = (long long)M * 16;
    const int gbN = (int)((n4N + 255) / 256);
    const int gbM = (int)((n4M + 255) / 256);

    // ---- block 1 (N rows, 32 -> 64) ----
    conv_kernel<32, 9><<<gN, 128>>>(feats, N, n331_1, N, Wt + o0, A, pS, pQ);
    bn_stage1<<<64, 256>>>(pS, pQ, gN, r1);
    bn_stage2<<<1, 64>>>(r1, N, st0);
    bnact_kernel<<<gbN, 256>>>((float4*)A, st0, n4N);
    conv_kernel<64, 9><<<gN, 128>>>(A, N, n313_1, N, Wt + o1, B, pS, pQ);
    bn_stage1<<<64, 256>>>(pS, pQ, gN, r1);
    bn_stage2<<<1, 64>>>(r1, N, st1);
    conv_kernel<32, 9><<<gN, 128>>>(feats, N, n313_1, N, Wt + o2, C, pS, pQ);
    bn_stage1<<<64, 256>>>(pS, pQ, gN, r1);
    bn_stage2<<<1, 64>>>(r1, N, st2);
    bnact_kernel<<<gbN, 256>>>((float4*)C, st2, n4N);
    conv_kernel<64, 9><<<gN, 128>>>(C, N, n331_1, N, Wt + o3, A, pS, pQ);
    bn_stage1<<<64, 256>>>(pS, pQ, gN, r1);
    bn_stage2<<<1, 64>>>(r1, N, st3);
    combine_kernel<<<gbN, 256>>>((const float4*)A, st3, (const float4*)B, st1,
                                 (float4*)C, n4N);

    // ---- pool (strided SparseConv3d, K=27): C (N rows) -> X1 (M rows) ----
    conv_kernel<64, 27><<<gM, 128>>>(C, N, pool_n, M, Wt + o4, X1, nullptr, nullptr);

    // ---- block 2 (M rows, dilation 2) ----
    conv_kernel<64, 9><<<gM, 128>>>(X1, M, n331_2, M, Wt + o5, A, pS, pQ);
    bn_stage1<<<64, 256>>>(pS, pQ, gM, r1);
    bn_stage2<<<1, 64>>>(r1, M, st0);
    bnact_kernel<<<gbM, 256>>>((float4*)A, st0, n4M);
    conv_kernel<64, 9><<<gM, 128>>>(A, M, n313_2, M, Wt + o6, B, pS, pQ);
    bn_stage1<<<64, 256>>>(pS, pQ, gM, r1);
    bn_stage2<<<1, 64>>>(r1, M, st1);
    conv_kernel<64, 9><<<gM, 128>>>(X1, M, n313_2, M, Wt + o7, C, pS, pQ);
    bn_stage1<<<64, 256>>>(pS, pQ, gM, r1);
    bn_stage2<<<1, 64>>>(r1, M, st2);
    bnact_kernel<<<gbM, 256>>>((float4*)C, st2, n4M);
    conv_kernel<64, 9><<<gM, 128>>>(C, M, n331_2, M, Wt + o8, A, pS, pQ);
    bn_stage1<<<64, 256>>>(pS, pQ, gM, r1);
    bn_stage2<<<1, 64>>>(r1, M, st3);
    combine_kernel<<<gbM, 256>>>((const float4*)A, st3, (const float4*)B, st1,
                                 (float4*)X2, n4M);

    // ---- block 3 (M rows, dilation 3) ----
    conv_kernel<64, 9><<<gM, 128>>>(X2, M, n331_3, M, Wt + o9, A, pS, pQ);
    bn_stage1<<<64, 256>>>(pS, pQ, gM, r1);
    bn_stage2<<<1, 64>>>(r1, M, st0);
    bnact_kernel<<<gbM, 256>>>((float4*)A, st0, n4M);
    conv_kernel<64, 9><<<gM, 128>>>(A, M, n313_3, M, Wt + o10, B, pS, pQ);
    bn_stage1<<<64, 256>>>(pS, pQ, gM, r1);
    bn_stage2<<<1, 64>>>(r1, M, st1);
    conv_kernel<64, 9><<<gM, 128>>>(X2, M, n313_3, M, Wt + o11, C, pS, pQ);
    bn_stage1<<<64, 256>>>(pS, pQ, gM, r1);
    bn_stage2<<<1, 64>>>(r1, M, st2);
    bnact_kernel<<<gbM, 256>>>((float4*)C, st2, n4M);
    conv_kernel<64, 9><<<gM, 128>>>(C, M, n331_3, M, Wt + o12, A, pS, pQ);
    bn_stage1<<<64, 256>>>(pS, pQ, gM, r1);
    bn_stage2<<<1, 64>>>(r1, M, st3);
    combine_kernel<<<gbM, 256>>>((const float4*)A, st3, (const float4*)B, st1,
                                 (float4*)X3, n4M);

    // ---- final 1x1 fuse ----
    final_kernel<<<gM, 128>>>(X1, X2, X3, Wt + o13, (float*)d_out, M);
}

// round 4
// speedup vs baseline: 2.5882x; 1.1522x over previous
#include <cuda_runtime.h>
#include <cstdint>

typedef unsigned long long u64;

// ---------------------------------------------------------------------------
// dilate_block — sparse-conv residual pyramid, round 4:
//   * warp-autonomous conv: each warp owns an 8-row tile, gathers via
//     cp.async double-buffer, syncs only with wait_group + __syncwarp
//     (no per-tap block barriers -> no convoying)
//   * each lane computes 2 output channels (co = l, l+32) x 8 rows
//   * fma.rn.f32x2 packed over adjacent input channels
//   * weights packed [K][CIN/4][64][4]
// ---------------------------------------------------------------------------

static constexpr int MAXR = 640000;        // hard bound on row count
static constexpr int MAXBLK = MAXR / 64 + 2;

// scratch (static __device__: allocation-free rule)
__device__ __align__(16) float g_A [MAXR * 64];
__device__ __align__(16) float g_B [MAXR * 64];
__device__ __align__(16) float g_C [MAXR * 64];
__device__ __align__(16) float g_X1[MAXR * 64];
__device__ __align__(16) float g_X2[MAXR * 64];
__device__ __align__(16) float g_X3[MAXR * 64];
__device__ float g_pS[MAXBLK * 64];
__device__ float g_pQ[MAXBLK * 64];
__device__ float g_r1[64 * 128];
__device__ float g_st[4 * 128];            // 4 slots of [mean[64], rstd[64]]
__device__ __align__(16) float g_Wt[528384];

__device__ __forceinline__ u64 ffma2(u64 a, u64 b, u64 c) {
    u64 d;
    asm("fma.rn.f32x2 %0, %1, %2, %3;" : "=l"(d) : "l"(a), "l"(b), "l"(c));
    return d;
}

// ---------------------------------------------------------------------------
// fused weight transpose+pack: src [K][CIN][64] -> dst [K][CIN/4][64][4]
// ---------------------------------------------------------------------------
struct WPtrs { const float* p[14]; };

__global__ void __launch_bounds__(256)
wtrans_all(WPtrs w, float* __restrict__ dst)
{
    const int Ks[14]   = {9,9,9,9,27,9,9,9,9,9,9,9,9,3};
    const int CINs[14] = {32,64,32,64,64,64,64,64,64,64,64,64,64,64};
    const int offs[14] = {0,18432,55296,73728,110592,221184,258048,294912,
                          331776,368640,405504,442368,479232,516096};
    int b = blockIdx.x, i = 0;
    while (b >= Ks[i]) { b -= Ks[i]; ++i; }
    const int CIN = CINs[i];
    const float* src = w.p[i] + (size_t)b * CIN * 64;
    float* d = dst + offs[i] + (size_t)b * CIN * 64;
    for (int e = threadIdx.x; e < CIN * 64; e += 256) {
        const int ci = e >> 6, co = e & 63;
        const int q = ci >> 2, j = ci & 3;
        d[(q * 64 + co) * 4 + j] = src[e];
    }
}

// ---------------------------------------------------------------------------
// Warp-autonomous gather-GEMM sparse conv.
//   out[n, co] = sum_k sum_ci  in[nbr[k,n], ci] * W[k, ci, co]
// Each warp: 8 rows x 64 co. Lane l: co = {l, l+32}, all 8 rows.
// cp.async double buffer per warp; zfill for missing neighbors.
// Per-block column partial sums/sumsq (deterministic) for BN.
// ---------------------------------------------------------------------------
template <int CIN, int K, bool STATS>
__global__ void __launch_bounds__(256)
conv_kernel(const float* __restrict__ in, int nIn,
            const int* __restrict__ nbr, int nOut,
            const float* __restrict__ Wp,
            float* __restrict__ out,
            float* __restrict__ pSum, float* __restrict__ pSq)
{
    __shared__ __align__(16) float buf[8][2][8][CIN];
    __shared__ float redS[8][64];
    __shared__ float redQ[8][64];

    const int t = threadIdx.x;
    const int w = t >> 5;
    const int l = t & 31;
    const int rowBase = (blockIdx.x * 8 + w) * 8;

    // gather assignment: 4 lanes per row, each lane CIN/16 float4 chunks
    const int gr = l >> 2;                  // row 0..7
    const int gp = l & 3;                   // part 0..3
    const int grow = rowBase + gr;
    const bool rowOK = (grow < nOut);

    auto prefetch = [&](int k, int b) {
        int j = rowOK ? nbr[(size_t)k * nOut + grow] : nIn;
        const bool v = (j < nIn);
        const float* src = in + (size_t)(v ? j : 0) * CIN;
        const int sz = v ? 16 : 0;
        const uint32_t dbase = (uint32_t)__cvta_generic_to_shared(&buf[w][b][gr][0]);
#pragma unroll
        for (int i = 0; i < CIN / 16; ++i) {
            const int c4 = gp + 4 * i;
            asm volatile("cp.async.ca.shared.global [%0], [%1], 16, %2;\n"
                         :: "r"(dbase + c4 * 16), "l"(src + c4 * 4), "r"(sz));
        }
        asm volatile("cp.async.commit_group;\n");
    };

    u64 accA[8], accB[8];
#pragma unroll
    for (int r = 0; r < 8; ++r) { accA[r] = 0ull; accB[r] = 0ull; }

    prefetch(0, 0);

    for (int k = 0; k < K; ++k) {
        if (k + 1 < K) {
            prefetch(k + 1, (k + 1) & 1);
            asm volatile("cp.async.wait_group 1;\n");
        } else {
            asm volatile("cp.async.wait_group 0;\n");
        }
        __syncwarp();

        const float* wk = Wp + (size_t)k * (CIN * 64);
        const float* frow = &buf[w][k & 1][0][0];
#pragma unroll
        for (int q = 0; q < CIN / 4; ++q) {
            const ulonglong2 wa = *reinterpret_cast<const ulonglong2*>(wk + (q * 64 + l) * 4);
            const ulonglong2 wb = *reinterpret_cast<const ulonglong2*>(wk + (q * 64 + l + 32) * 4);
#pragma unroll
            for (int r = 0; r < 8; ++r) {
                const ulonglong2 s2 =
                    *reinterpret_cast<const ulonglong2*>(frow + r * CIN + q * 4);
                accA[r] = ffma2(s2.x, wa.x, accA[r]);
                accA[r] = ffma2(s2.y, wa.y, accA[r]);
                accB[r] = ffma2(s2.x, wb.x, accB[r]);
                accB[r] = ffma2(s2.y, wb.y, accB[r]);
            }
        }
        __syncwarp();   // all lanes done reading buf[k&1] before it is refilled
    }

    // epilogue: write outputs + per-lane column sums
    float sA = 0.f, qA = 0.f, sB = 0.f, qB = 0.f;
#pragma unroll
    for (int r = 0; r < 8; ++r) {
        const int orow = rowBase + r;
        if (orow < nOut) {
            const float vA = __uint_as_float((unsigned)accA[r]) +
                             __uint_as_float((unsigned)(accA[r] >> 32));
            const float vB = __uint_as_float((unsigned)accB[r]) +
                             __uint_as_float((unsigned)(accB[r] >> 32));
            out[(size_t)orow * 64 + l]      = vA;
            out[(size_t)orow * 64 + l + 32] = vB;
            sA += vA; qA += vA * vA;
            sB += vB; qB += vB * vB;
        }
    }

    if (STATS) {
        redS[w][l] = sA;  redS[w][l + 32] = sB;
        redQ[w][l] = qA;  redQ[w][l + 32] = qB;
        __syncthreads();
        if (t < 64) {
            float s = 0.f, q = 0.f;
#pragma unroll
            for (int ww = 0; ww < 8; ++ww) { s += redS[ww][t]; q += redQ[ww][t]; }
            pSum[(size_t)blockIdx.x * 64 + t] = s;
            pSq [(size_t)blockIdx.x * 64 + t] = q;
        }
    }
}

// ---------------------------------------------------------------------------
// BN stats, two-stage deterministic reduction
// ---------------------------------------------------------------------------
__global__ void __launch_bounds__(256)
bn_stage1(const float* __restrict__ pS, const float* __restrict__ pQ,
          int nB, float* __restrict__ r1)
{
    __shared__ float sh[2][4][64];
    const int t = threadIdx.x;
    const int co = t & 63;
    const int sub = t >> 6;
    float s = 0.f, q = 0.f;
    for (int b = blockIdx.x * 4 + sub; b < nB; b += 64 * 4) {
        s += pS[(size_t)b * 64 + co];
        q += pQ[(size_t)b * 64 + co];
    }
    sh[0][sub][co] = s;
    sh[1][sub][co] = q;
    __syncthreads();
    if (sub == 0) {
        r1[blockIdx.x * 128 + co] =
            (sh[0][0][co] + sh[0][1][co]) + (sh[0][2][co] + sh[0][3][co]);
        r1[blockIdx.x * 128 + 64 + co] =
            (sh[1][0][co] + sh[1][1][co]) + (sh[1][2][co] + sh[1][3][co]);
    }
}

__global__ void bn_stage2(const float* __restrict__ r1, int nRows, float* __restrict__ st)
{
    const int t = threadIdx.x;   // 64 threads
    float s = 0.f, q = 0.f;
#pragma unroll 8
    for (int b = 0; b < 64; ++b) {
        s += r1[b * 128 + t];
        q += r1[b * 128 + 64 + t];
    }
    const float inv = 1.0f / (float)nRows;
    const float m = s * inv;
    const float var = q * inv - m * m;
    st[t] = m;
    st[64 + t] = rsqrtf(var + 1e-5f);
}

// ---------------------------------------------------------------------------
// x = lrelu(bn(x)) in place (float4)
// ---------------------------------------------------------------------------
__global__ void bnact_kernel(float4* __restrict__ x, const float* __restrict__ st, long long n4)
{
    const long long i = (long long)blockIdx.x * blockDim.x + threadIdx.x;
    if (i >= n4) return;
    const int c = ((int)(i & 15)) * 4;
    float4 v = x[i];
    v.x = (v.x - st[c + 0]) * st[64 + c + 0];
    v.y = (v.y - st[c + 1]) * st[64 + c + 1];
    v.z = (v.z - st[c + 2]) * st[64 + c + 2];
    v.w = (v.w - st[c + 3]) * st[64 + c + 3];
    v.x = v.x > 0.f ? v.x : 0.01f * v.x;
    v.y = v.y > 0.f ? v.y : 0.01f * v.y;
    v.z = v.z > 0.f ? v.z : 0.01f * v.z;
    v.w = v.w > 0.f ? v.w : 0.01f * v.w;
    x[i] = v;
}

// ---------------------------------------------------------------------------
// x = lrelu(bn(a)) + lrelu(bn(b))  (residual merge, float4)
// ---------------------------------------------------------------------------
__global__ void combine_kernel(const float4* __restrict__ a, const float* __restrict__ sa,
                               const float4* __restrict__ b, const float* __restrict__ sb,
                               float4* __restrict__ o, long long n4)
{
    const long long i = (long long)blockIdx.x * blockDim.x + threadIdx.x;
    if (i >= n4) return;
    const int c = ((int)(i & 15)) * 4;
    float4 va = a[i];
    float4 vb = b[i];
    float4 r;
    float x;
    x = (va.x - sa[c + 0]) * sa[64 + c + 0]; x = x > 0.f ? x : 0.01f * x; r.x = x;
    x = (va.y - sa[c + 1]) * sa[64 + c + 1]; x = x > 0.f ? x : 0.01f * x; r.y = x;
    x = (va.z - sa[c + 2]) * sa[64 + c + 2]; x = x > 0.f ? x : 0.01f * x; r.z = x;
    x = (va.w - sa[c + 3]) * sa[64 + c + 3]; x = x > 0.f ? x : 0.01f * x; r.w = x;
    x = (vb.x - sb[c + 0]) * sb[64 + c + 0]; x = x > 0.f ? x : 0.01f * x; r.x += x;
    x = (vb.y - sb[c + 1]) * sb[64 + c + 1]; x = x > 0.f ? x : 0.01f * x; r.y += x;
    x = (vb.z - sb[c + 2]) * sb[64 + c + 2]; x = x > 0.f ? x : 0.01f * x; r.z += x;
    x = (vb.w - sb[c + 3]) * sb[64 + c + 3]; x = x > 0.f ? x : 0.01f * x; r.w += x;
    o[i] = r;
}

// ---------------------------------------------------------------------------
// out[m] = [x1 | x2 | x3] @ down_w  (warp-autonomous, same scheme, K=3 "taps")
// ---------------------------------------------------------------------------
__global__ void __launch_bounds__(256)
final_kernel(const float* __restrict__ X1, const float* __restrict__ X2,
             const float* __restrict__ X3, const float* __restrict__ Wp,
             float* __restrict__ out, int M)
{
    __shared__ __align__(16) float buf[8][2][8][64];
    const int t = threadIdx.x;
    const int w = t >> 5;
    const int l = t & 31;
    const int rowBase = (blockIdx.x * 8 + w) * 8;
    const int gr = l >> 2;
    const int gp = l & 3;
    const int grow = rowBase + gr;
    const bool rowOK = (grow < M);

    const float* srcs[3] = {X1, X2, X3};
    auto prefetch = [&](int s, int b) {
        const float* src = srcs[s] + (size_t)(rowOK ? grow : 0) * 64;
        const int sz = rowOK ? 16 : 0;
        const uint32_t dbase = (uint32_t)__cvta_generic_to_shared(&buf[w][b][gr][0]);
#pragma unroll
        for (int i = 0; i < 4; ++i) {
            const int c4 = gp + 4 * i;
            asm volatile("cp.async.ca.shared.global [%0], [%1], 16, %2;\n"
                         :: "r"(dbase + c4 * 16), "l"(src + c4 * 4), "r"(sz));
        }
        asm volatile("cp.async.commit_group;\n");
    };

    u64 accA[8], accB[8];
#pragma unroll
    for (int r = 0; r < 8; ++r) { accA[r] = 0ull; accB[r] = 0ull; }

    prefetch(0, 0);
    for (int s = 0; s < 3; ++s) {
        if (s + 1 < 3) {
            prefetch(s + 1, (s + 1) & 1);
            asm volatile("cp.async.wait_group 1;\n");
        } else {
            asm volatile("cp.async.wait_group 0;\n");
        }
        __syncwarp();
        const float* wk = Wp + (size_t)s * (64 * 64);
        const float* frow = &buf[w][s & 1][0][0];
#pragma unroll
        for (int q = 0; q < 16; ++q) {
            const ulonglong2 wa = *reinterpret_cast<const ulonglong2*>(wk + (q * 64 + l) * 4);
            const ulonglong2 wb = *reinterpret_cast<const ulonglong2*>(wk + (q * 64 + l + 32) * 4);
#pragma unroll
            for (int r = 0; r < 8; ++r) {
                const ulonglong2 s2 =
                    *reinterpret_cast<const ulonglong2*>(frow + r * 64 + q * 4);
                accA[r] = ffma2(s2.x, wa.x, accA[r]);
                accA[r] = ffma2(s2.y, wa.y, accA[r]);
                accB[r] = ffma2(s2.x, wb.x, accB[r]);
                accB[r] = ffma2(s2.y, wb.y, accB[r]);
            }
        }
        __syncwarp();
    }
#pragma unroll
    for (int r = 0; r < 8; ++r) {
        const int orow = rowBase + r;
        if (orow < M) {
            out[(size_t)orow * 64 + l] =
                __uint_as_float((unsigned)accA[r]) + __uint_as_float((unsigned)(accA[r] >> 32));
            out[(size_t)orow * 64 + l + 32] =
                __uint_as_float((unsigned)accB[r]) + __uint_as_float((unsigned)(accB[r] >> 32));
        }
    }
}

// ---------------------------------------------------------------------------
extern "C" void kernel_launch(void* const* d_in, const int* in_sizes, int n_in,
                              void* d_out, int out_size)
{
    const float* feats = (const float*)d_in[0];
    const int* n331_1 = (const int*)d_in[15];
    const int* n313_1 = (const int*)d_in[16];
    const int* pool_n = (const int*)d_in[17];
    const int* n331_2 = (const int*)d_in[18];
    const int* n313_2 = (const int*)d_in[19];
    const int* n331_3 = (const int*)d_in[20];
    const int* n313_3 = (const int*)d_in[21];

    const int N = in_sizes[0] / 32;
    const int M = out_size / 64;

    float *A, *B, *C, *X1, *X2, *X3, *pS, *pQ, *r1, *st, *Wt;
    cudaGetSymbolAddress((void**)&A,  g_A);
    cudaGetSymbolAddress((void**)&B,  g_B);
    cudaGetSymbolAddress((void**)&C,  g_C);
    cudaGetSymbolAddress((void**)&X1, g_X1);
    cudaGetSymbolAddress((void**)&X2, g_X2);
    cudaGetSymbolAddress((void**)&X3, g_X3);
    cudaGetSymbolAddress((void**)&pS, g_pS);
    cudaGetSymbolAddress((void**)&pQ, g_pQ);
    cudaGetSymbolAddress((void**)&r1, g_r1);
    cudaGetSymbolAddress((void**)&st, g_st);
    cudaGetSymbolAddress((void**)&Wt, g_Wt);
    float* st0 = st;
    float* st1 = st + 128;
    float* st2 = st + 256;
    float* st3 = st + 384;

    // packed weight offsets in g_Wt (floats)
    const size_t o0 = 0;        // b1_w1   (9,32)
    const size_t o1 = 18432;    // b1_w1_2 (9,64)
    const size_t o2 = 55296;    // b1_w2   (9,32)
    const size_t o3 = 73728;    // b1_w2_2 (9,64)
    const size_t o4 = 110592;   // pool    (27,64)
    const size_t o5 = 221184;   // b2_w1
    const size_t o6 = 258048;   // b2_w1_2
    const size_t o7 = 294912;   // b2_w2
    const size_t o8 = 331776;   // b2_w2_2
    const size_t o9 = 368640;   // b3_w1
    const size_t o10 = 405504;  // b3_w1_2
    const size_t o11 = 442368;  // b3_w2
    const size_t o12 = 479232;  // b3_w2_2
    const size_t o13 = 516096;  // down    (3,64)

    WPtrs wp;
    for (int i = 0; i < 14; ++i) wp.p[i] = (const float*)d_in[1 + i];
    wtrans_all<<<138, 256>>>(wp, Wt);

    const int gN = (N + 63) / 64;           // blocks of 8 warps x 8 rows
    const int gM = (M + 63) / 64;
    const long long n4N = (long long)N * 16;
    const long long n4M = (long long)M * 16;
    const int gbN = (int)((n4N + 255) / 256);
    const int gbM = (int)((n4M + 255) / 256);

    // ---- block 1 (N rows, 32 -> 64) ----
    conv_kernel<32, 9, true><<<gN, 256>>>(feats, N, n331_1, N, Wt + o0, A, pS, pQ);
    bn_stage1<<<64, 256>>>(pS, pQ, gN, r1);
    bn_stage2<<<1, 64>>>(r1, N, st0);
    bnact_kernel<<<gbN, 256>>>((float4*)A, st0, n4N);
    conv_kernel<64, 9, true><<<gN, 256>>>(A, N, n313_1, N, Wt + o1, B, pS, pQ);
    bn_stage1<<<64, 256>>>(pS, pQ, gN, r1);
    bn_stage2<<<1, 64>>>(r1, N, st1);
    conv_kernel<32, 9, true><<<gN, 256>>>(feats, N, n313_1, N, Wt + o2, C, pS, pQ);
    bn_stage1<<<64, 256>>>(pS, pQ, gN, r1);
    bn_stage2<<<1, 64>>>(r1, N, st2);
    bnact_kernel<<<gbN, 256>>>((float4*)C, st2, n4N);
    conv_kernel<64, 9, true><<<gN, 256>>>(C, N, n331_1, N, Wt + o3, A, pS, pQ);
    bn_stage1<<<64, 256>>>(pS, pQ, gN, r1);
    bn_stage2<<<1, 64>>>(r1, N, st3);
    combine_kernel<<<gbN, 256>>>((const float4*)A, st3, (const float4*)B, st1,
                                 (float4*)C, n4N);

    // ---- pool (strided SparseConv3d, K=27): C (N rows) -> X1 (M rows) ----
    conv_kernel<64, 27, false><<<gM, 256>>>(C, N, pool_n, M, Wt + o4, X1, nullptr, nullptr);

    // ---- block 2 (M rows, dilation 2) ----
    conv_kernel<64, 9, true><<<gM, 256>>>(X1, M, n331_2, M, Wt + o5, A, pS, pQ);
    bn_stage1<<<64, 256>>>(pS, pQ, gM, r1);
    bn_stage2<<<1, 64>>>(r1, M, st0);
    bnact_kernel<<<gbM, 256>>>((float4*)A, st0, n4M);
    conv_kernel<64, 9, true><<<gM, 256>>>(A, M, n313_2, M, Wt + o6, B, pS, pQ);
    bn_stage1<<<64, 256>>>(pS, pQ, gM, r1);
    bn_stage2<<<1, 64>>>(r1, M, st1);
    conv_kernel<64, 9, true><<<gM, 256>>>(X1, M, n313_2, M, Wt + o7, C, pS, pQ);
    bn_stage1<<<64, 256>>>(pS, pQ, gM, r1);
    bn_stage2<<<1, 64>>>(r1, M, st2);
    bnact_kernel<<<gbM, 256>>>((float4*)C, st2, n4M);
    conv_kernel<64, 9, true><<<gM, 256>>>(C, M, n331_2, M, Wt + o8, A, pS, pQ);
    bn_stage1<<<64, 256>>>(pS, pQ, gM, r1);
    bn_stage2<<<1, 64>>>(r1, M, st3);
    combine_kernel<<<gbM, 256>>>((const float4*)A, st3, (const float4*)B, st1,
                                 (float4*)X2, n4M);

    // ---- block 3 (M rows, dilation 3) ----
    conv_kernel<64, 9, true><<<gM, 256>>>(X2, M, n331_3, M, Wt + o9, A, pS, pQ);
    bn_stage1<<<64, 256>>>(pS, pQ, gM, r1);
    bn_stage2<<<1, 64>>>(r1, M, st0);
    bnact_kernel<<<gbM, 256>>>((float4*)A, st0, n4M);
    conv_kernel<64, 9, true><<<gM, 256>>>(A, M, n313_3, M, Wt + o10, B, pS, pQ);
    bn_stage1<<<64, 256>>>(pS, pQ, gM, r1);
    bn_stage2<<<1, 64>>>(r1, M, st1);
    conv_kernel<64, 9, true><<<gM, 256>>>(X2, M, n313_3, M, Wt + o11, C, pS, pQ);
    bn_stage1<<<64, 256>>>(pS, pQ, gM, r1);
    bn_stage2<<<1, 64>>>(r1, M, st2);
    bnact_kernel<<<gbM, 256>>>((float4*)C, st2, n4M);
    conv_kernel<64, 9, true><<<gM, 256>>>(C, M, n331_3, M, Wt + o12, A, pS, pQ);
    bn_stage1<<<64, 256>>>(pS, pQ, gM, r1);
    bn_stage2<<<1, 64>>>(r1, M, st3);
    combine_kernel<<<gbM, 256>>>((const float4*)A, st3, (const float4*)B, st1,
                                 (float4*)X3, n4M);

    // ---- final 1x1 fuse ----
    final_kernel<<<gM, 256>>>(X1, X2, X3, Wt + o13, (float*)d_out, M);
}

// round 6
// speedup vs baseline: 5.1719x; 1.9982x over previous
#include <cuda_runtime.h>
#include <cuda_bf16.h>
#include <cstdint>

typedef unsigned long long u64;

// ---------------------------------------------------------------------------
// dilate_block — round 6: mma.sync (bf16, m16n8k16) split-precision convs.
//   x = hi + lo (bf16);  D = Ah@Bh + Al@Bh + Ah@Bl  (fp32 accumulators)
//   warp-autonomous 16-row tiles, fragment-major smem staging,
//   weights pre-converted to fragment-major hi/lo layout in global.
// ---------------------------------------------------------------------------

static constexpr int MAXR = 640000;

__device__ __align__(16) float g_A [MAXR * 64];
__device__ __align__(16) float g_B [MAXR * 64];
__device__ __align__(16) float g_C [MAXR * 64];
__device__ __align__(16) float g_X1[MAXR * 64];
__device__ __align__(16) float g_X2[MAXR * 64];
__device__ __align__(16) float g_X3[MAXR * 64];
__device__ float g_r1[64 * 128];
__device__ float g_st[4 * 128];
__device__ __align__(16) float g_Wt[3 * 4096];          // down_w packed (fp32 path)
__device__ __align__(16) uint32_t g_Wb[516096];         // all conv weights, frag-major hi/lo

// ---------------- helpers ----------------
__device__ __forceinline__ uint32_t smem_u32(const void* p) {
    uint32_t a;
    asm("{ .reg .u64 t; cvta.to.shared.u64 t, %1; cvt.u32.u64 %0, t; }" : "=r"(a) : "l"(p));
    return a;
}
// pack two f32 -> bf16x2 {low half = first arg, high half = second arg}
__device__ __forceinline__ uint32_t cvt2(float lo, float hi) {
    uint32_t r;
    asm("cvt.rn.bf16x2.f32 %0, %1, %2;" : "=r"(r) : "f"(hi), "f"(lo));
    return r;
}
__device__ __forceinline__ uint32_t lds32(uint32_t a) {
    uint32_t v;
    asm volatile("ld.shared.b32 %0, [%1];" : "=r"(v) : "r"(a));
    return v;
}
__device__ __forceinline__ void lds64(uint32_t* v, uint32_t a) {
    asm volatile("ld.shared.v2.b32 {%0,%1}, [%2];" : "=r"(v[0]), "=r"(v[1]) : "r"(a));
}
__device__ __forceinline__ void st32(uint32_t a, uint32_t v) {
    asm volatile("st.shared.b32 [%0], %1;" :: "r"(a), "r"(v));
}
__device__ __forceinline__ void mma_bf16(float d[4], const uint32_t a[4], const uint32_t b[2]) {
    asm volatile(
        "mma.sync.aligned.m16n8k16.row.col.f32.bf16.bf16.f32 "
        "{%0,%1,%2,%3}, {%4,%5,%6,%7}, {%8,%9}, {%0,%1,%2,%3};"
        : "+f"(d[0]), "+f"(d[1]), "+f"(d[2]), "+f"(d[3])
        : "r"(a[0]), "r"(a[1]), "r"(a[2]), "r"(a[3]), "r"(b[0]), "r"(b[1]));
}
__device__ __forceinline__ u64 ffma2(u64 a, u64 b, u64 c) {
    u64 d;
    asm("fma.rn.f32x2 %0, %1, %2, %3;" : "=l"(d) : "l"(a), "l"(b), "l"(c));
    return d;
}

// ---------------------------------------------------------------------------
// weight prep: fp32 [K][CIN][64] -> fragment-major hi/lo bf16 per tap:
//   per tap: [term(hi,lo)][kt][nt(8)][lane(32)][reg(2)] b32 words
// b32 word low half = k-even element, high half = k-odd.
// ---------------------------------------------------------------------------
struct WPtrs { const float* p[13]; };

__global__ void __launch_bounds__(256)
wprep(WPtrs w, uint32_t* __restrict__ dst)
{
    const int nT[13]   = {9,9,9,9,27,9,9,9,9,9,9,9,9};
    const int cinA[13] = {32,64,32,64,64,64,64,64,64,64,64,64,64};
    const int offW[13] = {0,18432,55296,73728,110592,221184,258048,294912,
                          331776,368640,405504,442368,479232};
    int b = blockIdx.x, c = 0;
    while (b >= nT[c]) { b -= nT[c]; ++c; }
    const int CIN = cinA[c];
    const int KT = CIN / 16;
    const float* src = w.p[c] + (size_t)b * CIN * 64;
    uint16_t* hiT = reinterpret_cast<uint16_t*>(dst + offW[c] + (size_t)b * (KT * 1024));
    uint16_t* loT = hiT + KT * 1024;   // term stride = KT*512 words = KT*1024 u16
    for (int e = threadIdx.x; e < CIN * 64; e += 256) {
        const int ci = e >> 6, co = e & 63;
        const float x = src[e];
        __nv_bfloat16 hb = __float2bfloat16(x);
        __nv_bfloat16 lb = __float2bfloat16(x - __bfloat162float(hb));
        const int kt = ci >> 4, ck = (ci & 15) >> 1, j = ci & 1;
        const int regb = (ck >= 4) ? 1 : 0;
        const int tt = ck & 3, nt = co >> 3, gg = co & 7;
        const int word = ((kt * 8 + nt) * 32 + (gg * 4 + tt)) * 2 + regb;
        hiT[word * 2 + j] = *reinterpret_cast<unsigned short*>(&hb);
        loT[word * 2 + j] = *reinterpret_cast<unsigned short*>(&lb);
    }
}

// down_w pack for fp32 final kernel: [3][64][64] -> [3][16][64][4]
__global__ void wtrans_down(const float* __restrict__ src, float* __restrict__ dst)
{
    const int k = blockIdx.x;
    for (int e = threadIdx.x; e < 4096; e += 256) {
        const int ci = e >> 6, co = e & 63;
        dst[k * 4096 + ((ci >> 2) * 64 + co) * 4 + (ci & 3)] = src[k * 4096 + e];
    }
}

// ---------------------------------------------------------------------------
// mma.sync gather-GEMM conv: 256 thr, 8 warps x 16 rows = 128 rows per block.
//   out[n, co] = sum_k sum_ci in[nbr[k,n], ci] * W[k, ci, co]
// ---------------------------------------------------------------------------
template <int KTILES, int KTAPS>
__global__ void __launch_bounds__(256)
mma_conv(const float* __restrict__ in, int nIn,
         const int* __restrict__ nbr, int nOut,
         const uint32_t* __restrict__ Wg,
         float* __restrict__ out)
{
    constexpr int CIN = KTILES * 16;
    constexpr int CHUNK = 9;
    constexpr int TAPW = KTILES * 1024;              // b32 words per tap (hi+lo)
    constexpr int WSM_BYTES = CHUNK * TAPW * 4;
    constexpr int ATERM_BYTES = KTILES * 4 * 33 * 4; // stride-33 padded frag layout
    constexpr int ABUF_BYTES = 2 * ATERM_BYTES;
    constexpr int NF4 = CIN / 8;                     // float4 per gather lane

    extern __shared__ __align__(16) char smem[];
    const uint32_t sb = smem_u32(smem);
    const uint32_t wsm = sb;
    const uint32_t abase = sb + WSM_BYTES;

    const int t = threadIdx.x;
    const int w = t >> 5;
    const int l = t & 31;
    const int rowBase = blockIdx.x * 128 + w * 16;

    const int gr = l >> 1;                 // gather row 0..15
    const int part = l & 1;                // which half of the channels
    const int grow = rowBase + gr;
    const bool rowOK = (grow < nOut);

    const uint32_t abuf0 = abase + (uint32_t)(w * 2 + 0) * ABUF_BYTES;
    const uint32_t abuf1 = abase + (uint32_t)(w * 2 + 1) * ABUF_BYTES;

    float4 pf[NF4];
    auto prefetch = [&](int k) {
        const int j = rowOK ? __ldg(&nbr[(size_t)k * nOut + grow]) : nIn;
        if (j < nIn) {
            const float4* s = reinterpret_cast<const float4*>(in + (size_t)j * CIN) + part * NF4;
#pragma unroll
            for (int i = 0; i < NF4; ++i) pf[i] = s[i];
        } else {
#pragma unroll
            for (int i = 0; i < NF4; ++i) pf[i] = make_float4(0.f, 0.f, 0.f, 0.f);
        }
    };
    // write pf -> fragment-major smem (hi term at buf, lo term at +ATERM_BYTES)
    auto convert_sts = [&](uint32_t buf) {
#pragma unroll
        for (int i = 0; i < NF4; ++i) {
            const int kt = (KTILES == 4) ? (part * 2 + (i >> 2)) : part;
            const int regb = ((gr >> 3) & 1) | ((i & 2) ? 2 : 0);
            const int lane0 = ((gr & 7) << 2) + ((i & 1) << 1);
            const uint32_t w0 = (uint32_t)(((kt * 4 + regb) * 33 + lane0) * 4);
            const float4 x = pf[i];
            const uint32_t h0 = cvt2(x.x, x.y);
            const uint32_t h1 = cvt2(x.z, x.w);
            const float l0 = x.x - __uint_as_float(h0 << 16);
            const float l1 = x.y - __uint_as_float(h0 & 0xFFFF0000u);
            const float l2 = x.z - __uint_as_float(h1 << 16);
            const float l3 = x.w - __uint_as_float(h1 & 0xFFFF0000u);
            const uint32_t q0 = cvt2(l0, l1);
            const uint32_t q1 = cvt2(l2, l3);
            st32(buf + w0, h0);
            st32(buf + w0 + 4, h1);
            st32(buf + ATERM_BYTES + w0, q0);
            st32(buf + ATERM_BYTES + w0 + 4, q1);
        }
    };

    float acc[8][4];
#pragma unroll
    for (int nt = 0; nt < 8; ++nt)
#pragma unroll
        for (int j = 0; j < 4; ++j) acc[nt][j] = 0.f;

    prefetch(0);
    convert_sts(abuf0);
    __syncwarp();

    for (int c = 0; c < KTAPS / CHUNK; ++c) {
        if (c > 0) __syncthreads();
        // stage this chunk's weights (whole block)
        {
            const char* src = reinterpret_cast<const char*>(Wg + (size_t)c * CHUNK * TAPW);
            for (int o = t * 16; o < WSM_BYTES; o += 256 * 16) {
                asm volatile("cp.async.ca.shared.global [%0], [%1], 16;"
                             :: "r"(wsm + (uint32_t)o), "l"(src + o));
            }
            asm volatile("cp.async.commit_group;");
            asm volatile("cp.async.wait_group 0;");
        }
        __syncthreads();

        for (int kk = 0; kk < CHUNK; ++kk) {
            const int k = c * CHUNK + kk;
            const uint32_t cur = (k & 1) ? abuf1 : abuf0;
            const uint32_t nxt = (k & 1) ? abuf0 : abuf1;
            if (k + 1 < KTAPS) prefetch(k + 1);
            const uint32_t wtap = wsm + (uint32_t)(kk * TAPW * 4);
#pragma unroll
            for (int kt = 0; kt < KTILES; ++kt) {
                uint32_t ah[4], al[4];
#pragma unroll
                for (int j = 0; j < 4; ++j) {
                    const uint32_t ao = (uint32_t)(((kt * 4 + j) * 33 + l) * 4);
                    ah[j] = lds32(cur + ao);
                    al[j] = lds32(cur + ATERM_BYTES + ao);
                }
#pragma unroll
                for (int nt = 0; nt < 8; ++nt) {
                    uint32_t bh[2], bl[2];
                    const uint32_t boff = wtap + (uint32_t)((((kt * 8 + nt) * 32 + l) * 2) * 4);
                    lds64(bh, boff);
                    lds64(bl, boff + (uint32_t)(KTILES * 2048));
                    mma_bf16(acc[nt], ah, bh);
                    mma_bf16(acc[nt], al, bh);
                    mma_bf16(acc[nt], ah, bl);
                }
            }
            if (k + 1 < KTAPS) convert_sts(nxt);
            __syncwarp();
        }
    }

    // epilogue: D frag -> out
    const int dg = l >> 2, dt = l & 3;
    const int row0 = rowBase + dg;
    const int row1 = rowBase + dg + 8;
    if (row0 < nOut) {
        float* o = out + (size_t)row0 * 64 + dt * 2;
#pragma unroll
        for (int nt = 0; nt < 8; ++nt)
            *reinterpret_cast<float2*>(o + nt * 8) = make_float2(acc[nt][0], acc[nt][1]);
    }
    if (row1 < nOut) {
        float* o = out + (size_t)row1 * 64 + dt * 2;
#pragma unroll
        for (int nt = 0; nt < 8; ++nt)
            *reinterpret_cast<float2*>(o + nt * 8) = make_float2(acc[nt][2], acc[nt][3]);
    }
}

// ---------------------------------------------------------------------------
// BN stats from conv output (deterministic two-stage)
// ---------------------------------------------------------------------------
__global__ void __launch_bounds__(256)
bn_stage1(const float* __restrict__ x, int nRows, float* __restrict__ r1)
{
    __shared__ float sh[2][4][64];
    const int t = threadIdx.x;
    const int co = t & 63;
    const int sub = t >> 6;
    float s = 0.f, q = 0.f;
    for (int row = blockIdx.x * 4 + sub; row < nRows; row += 256) {
        const float v = x[(size_t)row * 64 + co];
        s += v;
        q += v * v;
    }
    sh[0][sub][co] = s;
    sh[1][sub][co] = q;
    __syncthreads();
    if (sub == 0) {
        r1[blockIdx.x * 128 + co] =
            (sh[0][0][co] + sh[0][1][co]) + (sh[0][2][co] + sh[0][3][co]);
        r1[blockIdx.x * 128 + 64 + co] =
            (sh[1][0][co] + sh[1][1][co]) + (sh[1][2][co] + sh[1][3][co]);
    }
}

__global__ void bn_stage2(const float* __restrict__ r1, int nRows, float* __restrict__ st)
{
    const int t = threadIdx.x;   // 64 threads
    float s = 0.f, q = 0.f;
#pragma unroll 8
    for (int b = 0; b < 64; ++b) {
        s += r1[b * 128 + t];
        q += r1[b * 128 + 64 + t];
    }
    const float inv = 1.0f / (float)nRows;
    const float m = s * inv;
    const float var = q * inv - m * m;
    st[t] = m;
    st[64 + t] = rsqrtf(var + 1e-5f);
}

__global__ void bnact_kernel(float4* __restrict__ x, const float* __restrict__ st, long long n4)
{
    const long long i = (long long)blockIdx.x * blockDim.x + threadIdx.x;
    if (i >= n4) return;
    const int c = ((int)(i & 15)) * 4;
    float4 v = x[i];
    v.x = (v.x - st[c + 0]) * st[64 + c + 0];
    v.y = (v.y - st[c + 1]) * st[64 + c + 1];
    v.z = (v.z - st[c + 2]) * st[64 + c + 2];
    v.w = (v.w - st[c + 3]) * st[64 + c + 3];
    v.x = v.x > 0.f ? v.x : 0.01f * v.x;
    v.y = v.y > 0.f ? v.y : 0.01f * v.y;
    v.z = v.z > 0.f ? v.z : 0.01f * v.z;
    v.w = v.w > 0.f ? v.w : 0.01f * v.w;
    x[i] = v;
}

__global__ void combine_kernel(const float4* __restrict__ a, const float* __restrict__ sa,
                               const float4* __restrict__ b, const float* __restrict__ sb,
                               float4* __restrict__ o, long long n4)
{
    const long long i = (long long)blockIdx.x * blockDim.x + threadIdx.x;
    if (i >= n4) return;
    const int c = ((int)(i & 15)) * 4;
    float4 va = a[i];
    float4 vb = b[i];
    float4 r;
    float x;
    x = (va.x - sa[c + 0]) * sa[64 + c + 0]; x = x > 0.f ? x : 0.01f * x; r.x = x;
    x = (va.y - sa[c + 1]) * sa[64 + c + 1]; x = x > 0.f ? x : 0.01f * x; r.y = x;
    x = (va.z - sa[c + 2]) * sa[64 + c + 2]; x = x > 0.f ? x : 0.01f * x; r.z = x;
    x = (va.w - sa[c + 3]) * sa[64 + c + 3]; x = x > 0.f ? x : 0.01f * x; r.w = x;
    x = (vb.x - sb[c + 0]) * sb[64 + c + 0]; x = x > 0.f ? x : 0.01f * x; r.x += x;
    x = (vb.y - sb[c + 1]) * sb[64 + c + 1]; x = x > 0.f ? x : 0.01f * x; r.y += x;
    x = (vb.z - sb[c + 2]) * sb[64 + c + 2]; x = x > 0.f ? x : 0.01f * x; r.z += x;
    x = (vb.w - sb[c + 3]) * sb[64 + c + 3]; x = x > 0.f ? x : 0.01f * x; r.w += x;
    o[i] = r;
}

// out[m] = [x1 | x2 | x3] @ down_w  (fp32 FFMA2 path, warp-autonomous)
__global__ void __launch_bounds__(256)
final_kernel(const float* __restrict__ X1, const float* __restrict__ X2,
             const float* __restrict__ X3, const float* __restrict__ Wp,
             float* __restrict__ out, int M)
{
    __shared__ __align__(16) float buf[8][2][8][64];
    const int t = threadIdx.x;
    const int w = t >> 5;
    const int l = t & 31;
    const int rowBase = (blockIdx.x * 8 + w) * 8;
    const int gr = l >> 2;
    const int gp = l & 3;
    const int grow = rowBase + gr;
    const bool rowOK = (grow < M);

    const float* srcs[3] = {X1, X2, X3};
    auto prefetch = [&](int s, int b) {
        const float* src = srcs[s] + (size_t)(rowOK ? grow : 0) * 64;
        const int sz = rowOK ? 16 : 0;
        const uint32_t dbase = (uint32_t)__cvta_generic_to_shared(&buf[w][b][gr][0]);
#pragma unroll
        for (int i = 0; i < 4; ++i) {
            const int c4 = gp + 4 * i;
            asm volatile("cp.async.ca.shared.global [%0], [%1], 16, %2;\n"
                         :: "r"(dbase + c4 * 16), "l"(src + c4 * 4), "r"(sz));
        }
        asm volatile("cp.async.commit_group;\n");
    };

    u64 accA[8], accB[8];
#pragma unroll
    for (int r = 0; r < 8; ++r) { accA[r] = 0ull; accB[r] = 0ull; }

    prefetch(0, 0);
    for (int s = 0; s < 3; ++s) {
        if (s + 1 < 3) {
            prefetch(s + 1, (s + 1) & 1);
            asm volatile("cp.async.wait_group 1;\n");
        } else {
            asm volatile("cp.async.wait_group 0;\n");
        }
        __syncwarp();
        const float* wk = Wp + (size_t)s * (64 * 64);
        const float* frow = &buf[w][s & 1][0][0];
#pragma unroll
        for (int q = 0; q < 16; ++q) {
            const ulonglong2 wa = *reinterpret_cast<const ulonglong2*>(wk + (q * 64 + l) * 4);
            const ulonglong2 wb = *reinterpret_cast<const ulonglong2*>(wk + (q * 64 + l + 32) * 4);
#pragma unroll
            for (int r = 0; r < 8; ++r) {
                const ulonglong2 s2 =
                    *reinterpret_cast<const ulonglong2*>(frow + r * 64 + q * 4);
                accA[r] = ffma2(s2.x, wa.x, accA[r]);
                accA[r] = ffma2(s2.y, wa.y, accA[r]);
                accB[r] = ffma2(s2.x, wb.x, accB[r]);
                accB[r] = ffma2(s2.y, wb.y, accB[r]);
            }
        }
        __syncwarp();
    }
#pragma unroll
    for (int r = 0; r < 8; ++r) {
        const int orow = rowBase + r;
        if (orow < M) {
            out[(size_t)orow * 64 + l] =
                __uint_as_float((unsigned)accA[r]) + __uint_as_float((unsigned)(accA[r] >> 32));
            out[(size_t)orow * 64 + l + 32] =
                __uint_as_float((unsigned)accB[r]) + __uint_as_float((unsigned)(accB[r] >> 32));
        }
    }
}

// ---------------------------------------------------------------------------
extern "C" void kernel_launch(void* const* d_in, const int* in_sizes, int n_in,
                              void* d_out, int out_size)
{
    const float* feats  = (const float*)d_in[0];
    const float* down_w = (const float*)d_in[14];
    const int* n331_1 = (const int*)d_in[15];
    const int* n313_1 = (const int*)d_in[16];
    const int* pool_n = (const int*)d_in[17];
    const int* n331_2 = (const int*)d_in[18];
    const int* n313_2 = (const int*)d_in[19];
    const int* n331_3 = (const int*)d_in[20];
    const int* n313_3 = (const int*)d_in[21];

    const int N = in_sizes[0] / 32;
    const int M = out_size / 64;

    float *A, *B, *C, *X1, *X2, *X3, *r1, *st, *Wt;
    uint32_t* Wb;
    cudaGetSymbolAddress((void**)&A,  g_A);
    cudaGetSymbolAddress((void**)&B,  g_B);
    cudaGetSymbolAddress((void**)&C,  g_C);
    cudaGetSymbolAddress((void**)&X1, g_X1);
    cudaGetSymbolAddress((void**)&X2, g_X2);
    cudaGetSymbolAddress((void**)&X3, g_X3);
    cudaGetSymbolAddress((void**)&r1, g_r1);
    cudaGetSymbolAddress((void**)&st, g_st);
    cudaGetSymbolAddress((void**)&Wt, g_Wt);
    cudaGetSymbolAddress((void**)&Wb, g_Wb);
    float* st0 = st;
    float* st1 = st + 128;
    float* st2 = st + 256;
    float* st3 = st + 384;

    // weight word offsets (b32) per conv, frag-major layout
    const size_t o0 = 0;        // b1_w1   (9 taps, CIN=32)
    const size_t o1 = 18432;    // b1_w1_2
    const size_t o2 = 55296;    // b1_w2   (CIN=32)
    const size_t o3 = 73728;    // b1_w2_2
    const size_t o4 = 110592;   // pool (27 taps)
    const size_t o5 = 221184;   // b2_w1
    const size_t o6 = 258048;   // b2_w1_2
    const size_t o7 = 294912;   // b2_w2
    const size_t o8 = 331776;   // b2_w2_2
    const size_t o9 = 368640;   // b3_w1
    const size_t o10 = 405504;  // b3_w1_2
    const size_t o11 = 442368;  // b3_w2
    const size_t o12 = 479232;  // b3_w2_2

    // dynamic smem: chunk weights + A frag buffers
    const int SM2 = 9 * (2 * 1024) * 4 + 16 * (2 * (2 * 4 * 33 * 4));   // 73728 + 33792
    const int SM4 = 9 * (4 * 1024) * 4 + 16 * (2 * (4 * 4 * 33 * 4));   // 147456 + 67584
    cudaFuncSetAttribute(mma_conv<2, 9>,  cudaFuncAttributeMaxDynamicSharedMemorySize, SM2);
    cudaFuncSetAttribute(mma_conv<4, 9>,  cudaFuncAttributeMaxDynamicSharedMemorySize, SM4);
    cudaFuncSetAttribute(mma_conv<4, 27>, cudaFuncAttributeMaxDynamicSharedMemorySize, SM4);

    WPtrs wp;
    for (int i = 0; i < 13; ++i) wp.p[i] = (const float*)d_in[1 + i];
    wprep<<<135, 256>>>(wp, Wb);
    wtrans_down<<<3, 256>>>(down_w, Wt);

    const int gN = (N + 127) / 128;
    const int gM = (M + 127) / 128;
    const long long n4N = (long long)N * 16;
    const long long n4M = (long long)M * 16;
    const int gbN = (int)((n4N + 255) / 256);
    const int gbM = (int)((n4M + 255) / 256);
    const int gMf = (M + 63) / 64;

    // ---- block 1 (N rows, 32 -> 64) ----
    mma_conv<2, 9><<<gN, 256, SM2>>>(feats, N, n331_1, N, Wb + o0, A);
    bn_stage1<<<64, 256>>>(A, N, r1);
    bn_stage2<<<1, 64>>>(r1, N, st0);
    bnact_kernel<<<gbN, 256>>>((float4*)A, st0, n4N);
    mma_conv<4, 9><<<gN, 256, SM4>>>(A, N, n313_1, N, Wb + o1, B);
    bn_stage1<<<64, 256>>>(B, N, r1);
    bn_stage2<<<1, 64>>>(r1, N, st1);
    mma_conv<2, 9><<<gN, 256, SM2>>>(feats, N, n313_1, N, Wb + o2, C);
    bn_stage1<<<64, 256>>>(C, N, r1);
    bn_stage2<<<1, 64>>>(r1, N, st2);
    bnact_kernel<<<gbN, 256>>>((float4*)C, st2, n4N);
    mma_conv<4, 9><<<gN, 256, SM4>>>(C, N, n331_1, N, Wb + o3, A);
    bn_stage1<<<64, 256>>>(A, N, r1);
    bn_stage2<<<1, 64>>>(r1, N, st3);
    combine_kernel<<<gbN, 256>>>((const float4*)A, st3, (const float4*)B, st1,
                                 (float4*)C, n4N);

    // ---- pool (K=27): C (N rows) -> X1 (M rows) ----
    mma_conv<4, 27><<<gM, 256, SM4>>>(C, N, pool_n, M, Wb + o4, X1);

    // ---- block 2 (M rows, dilation 2) ----
    mma_conv<4, 9><<<gM, 256, SM4>>>(X1, M, n331_2, M, Wb + o5, A);
    bn_stage1<<<64, 256>>>(A, M, r1);
    bn_stage2<<<1, 64>>>(r1, M, st0);
    bnact_kernel<<<gbM, 256>>>((float4*)A, st0, n4M);
    mma_conv<4, 9><<<gM, 256, SM4>>>(A, M, n313_2, M, Wb + o6, B);
    bn_stage1<<<64, 256>>>(B, M, r1);
    bn_stage2<<<1, 64>>>(r1, M, st1);
    mma_conv<4, 9><<<gM, 256, SM4>>>(X1, M, n313_2, M, Wb + o7, C);
    bn_stage1<<<64, 256>>>(C, M, r1);
    bn_stage2<<<1, 64>>>(r1, M, st2);
    bnact_kernel<<<gbM, 256>>>((float4*)C, st2, n4M);
    mma_conv<4, 9><<<gM, 256, SM4>>>(C, M, n331_2, M, Wb + o8, A);
    bn_stage1<<<64, 256>>>(A, M, r1);
    bn_stage2<<<1, 64>>>(r1, M, st3);
    combine_kernel<<<gbM, 256>>>((const float4*)A, st3, (const float4*)B, st1,
                                 (float4*)X2, n4M);

    // ---- block 3 (M rows, dilation 3) ----
    mma_conv<4, 9><<<gM, 256, SM4>>>(X2, M, n331_3, M, Wb + o9, A);
    bn_stage1<<<64, 256>>>(A, M, r1);
    bn_stage2<<<1, 64>>>(r1, M, st0);
    bnact_kernel<<<gbM, 256>>>((float4*)A, st0, n4M);
    mma_conv<4, 9><<<gM, 256, SM4>>>(A, M, n313_3, M, Wb + o10, B);
    bn_stage1<<<64, 256>>>(B, M, r1);
    bn_stage2<<<1, 64>>>(r1, M, st1);
    mma_conv<4, 9><<<gM, 256, SM4>>>(X2, M, n313_3, M, Wb + o11, C);
    bn_stage1<<<64, 256>>>(C, M, r1);
    bn_stage2<<<1, 64>>>(r1, M, st2);
    bnact_kernel<<<gbM, 256>>>((float4*)C, st2, n4M);
    mma_conv<4, 9><<<gM, 256, SM4>>>(C, M, n331_3, M, Wb + o12, A);
    bn_stage1<<<64, 256>>>(A, M, r1);
    bn_stage2<<<1, 64>>>(r1, M, st3);
    combine_kernel<<<gbM, 256>>>((const float4*)A, st3, (const float4*)B, st1,
                                 (float4*)X3, n4M);

    // ---- final 1x1 fuse ----
    final_kernel<<<gMf, 256>>>(X1, X2, X3, Wt, (float*)d_out, M);
}

// round 7
// speedup vs baseline: 6.3455x; 1.2269x over previous
#include <cuda_runtime.h>
#include <cuda_bf16.h>
#include <cstdint>

typedef unsigned long long u64;

// ---------------------------------------------------------------------------
// dilate_block — round 7: mma.sync bf16 split-precision convs,
//   * B fragments via __ldg from global (L1-resident) -> smem 215KB -> 72KB
//   * BN stats fused into conv epilogue (shfl + ticket last-CTA reduce)
//   * fully warp-autonomous mainloop (no block barriers)
// ---------------------------------------------------------------------------

static constexpr int MAXR = 640000;
static constexpr int MAXBLK = MAXR / 128 + 2;

__device__ __align__(16) float g_A [MAXR * 64];
__device__ __align__(16) float g_B [MAXR * 64];
__device__ __align__(16) float g_C [MAXR * 64];
__device__ __align__(16) float g_X1[MAXR * 64];
__device__ __align__(16) float g_X2[MAXR * 64];
__device__ __align__(16) float g_X3[MAXR * 64];
__device__ float g_pS[MAXBLK * 64];
__device__ float g_pQ[MAXBLK * 64];
__device__ float g_st[4 * 128];
__device__ unsigned g_tick;                             // zero-init, self-resetting
__device__ __align__(16) float g_Wt[3 * 4096];          // down_w packed (fp32 path)
__device__ __align__(16) uint32_t g_Wb[516096];         // conv weights, frag-major hi/lo

// ---------------- helpers ----------------
__device__ __forceinline__ uint32_t smem_u32(const void* p) {
    uint32_t a;
    asm("{ .reg .u64 t; cvta.to.shared.u64 t, %1; cvt.u32.u64 %0, t; }" : "=r"(a) : "l"(p));
    return a;
}
__device__ __forceinline__ uint32_t cvt2(float lo, float hi) {
    uint32_t r;
    asm("cvt.rn.bf16x2.f32 %0, %1, %2;" : "=r"(r) : "f"(hi), "f"(lo));
    return r;
}
__device__ __forceinline__ uint32_t lds32(uint32_t a) {
    uint32_t v;
    asm volatile("ld.shared.b32 %0, [%1];" : "=r"(v) : "r"(a));
    return v;
}
__device__ __forceinline__ void st32(uint32_t a, uint32_t v) {
    asm volatile("st.shared.b32 [%0], %1;" :: "r"(a), "r"(v));
}
__device__ __forceinline__ void mma_bf16(float d[4], const uint32_t a[4], const uint32_t b[2]) {
    asm volatile(
        "mma.sync.aligned.m16n8k16.row.col.f32.bf16.bf16.f32 "
        "{%0,%1,%2,%3}, {%4,%5,%6,%7}, {%8,%9}, {%0,%1,%2,%3};"
        : "+f"(d[0]), "+f"(d[1]), "+f"(d[2]), "+f"(d[3])
        : "r"(a[0]), "r"(a[1]), "r"(a[2]), "r"(a[3]), "r"(b[0]), "r"(b[1]));
}
__device__ __forceinline__ u64 ffma2(u64 a, u64 b, u64 c) {
    u64 d;
    asm("fma.rn.f32x2 %0, %1, %2, %3;" : "=l"(d) : "l"(a), "l"(b), "l"(c));
    return d;
}

// ---------------------------------------------------------------------------
// weight prep: fp32 [K][CIN][64] -> per tap [term(hi,lo)][kt][nt(8)][lane(32)][reg(2)]
// ---------------------------------------------------------------------------
struct WPtrs { const float* p[13]; };

__global__ void __launch_bounds__(256)
wprep(WPtrs w, uint32_t* __restrict__ dst)
{
    const int nT[13]   = {9,9,9,9,27,9,9,9,9,9,9,9,9};
    const int cinA[13] = {32,64,32,64,64,64,64,64,64,64,64,64,64};
    const int offW[13] = {0,18432,55296,73728,110592,221184,258048,294912,
                          331776,368640,405504,442368,479232};
    int b = blockIdx.x, c = 0;
    while (b >= nT[c]) { b -= nT[c]; ++c; }
    const int CIN = cinA[c];
    const int KT = CIN / 16;
    const float* src = w.p[c] + (size_t)b * CIN * 64;
    uint16_t* hiT = reinterpret_cast<uint16_t*>(dst + offW[c] + (size_t)b * (KT * 1024));
    uint16_t* loT = hiT + KT * 1024;
    for (int e = threadIdx.x; e < CIN * 64; e += 256) {
        const int ci = e >> 6, co = e & 63;
        const float x = src[e];
        __nv_bfloat16 hb = __float2bfloat16(x);
        __nv_bfloat16 lb = __float2bfloat16(x - __bfloat162float(hb));
        const int kt = ci >> 4, ck = (ci & 15) >> 1, j = ci & 1;
        const int regb = (ck >= 4) ? 1 : 0;
        const int tt = ck & 3, nt = co >> 3, gg = co & 7;
        const int word = ((kt * 8 + nt) * 32 + (gg * 4 + tt)) * 2 + regb;
        hiT[word * 2 + j] = *reinterpret_cast<unsigned short*>(&hb);
        loT[word * 2 + j] = *reinterpret_cast<unsigned short*>(&lb);
    }
}

__global__ void wtrans_down(const float* __restrict__ src, float* __restrict__ dst)
{
    const int k = blockIdx.x;
    for (int e = threadIdx.x; e < 4096; e += 256) {
        const int ci = e >> 6, co = e & 63;
        dst[k * 4096 + ((ci >> 2) * 64 + co) * 4 + (ci & 3)] = src[k * 4096 + e];
    }
}

// ---------------------------------------------------------------------------
// mma.sync gather-GEMM conv. 256 thr, 8 warps x 16 rows = 128 rows per block.
// B fragments from global (__ldg). Optional fused BN stats (ticket reduce).
// ---------------------------------------------------------------------------
template <int KTILES, int KTAPS, bool STATS>
__global__ void __launch_bounds__(256, 2)
mma_conv(const float* __restrict__ in, int nIn,
         const int* __restrict__ nbr, int nOut,
         const uint32_t* __restrict__ Wg,
         float* __restrict__ out,
         float* __restrict__ pSum, float* __restrict__ pSq,
         float* __restrict__ stOut)
{
    constexpr int CIN = KTILES * 16;
    constexpr int TAPW = KTILES * 1024;              // b32 words per tap (hi+lo)
    constexpr int LOW = KTILES * 512;                // lo-block word offset within tap
    constexpr int ATERM_BYTES = KTILES * 4 * 33 * 4; // stride-33 padded frag layout
    constexpr int ABUF_BYTES = 2 * ATERM_BYTES;
    constexpr int NF4 = CIN / 8;

    extern __shared__ __align__(16) char smem[];
    __shared__ float redS[8][64];
    __shared__ float redQ[8][64];
    __shared__ unsigned s_last;

    const uint32_t abase = smem_u32(smem);
    const int t = threadIdx.x;
    const int w = t >> 5;
    const int l = t & 31;
    const int rowBase = blockIdx.x * 128 + w * 16;

    const int gr = l >> 1;
    const int part = l & 1;
    const int grow = rowBase + gr;
    const bool rowOK = (grow < nOut);

    const uint32_t abuf0 = abase + (uint32_t)(w * 2 + 0) * ABUF_BYTES;
    const uint32_t abuf1 = abase + (uint32_t)(w * 2 + 1) * ABUF_BYTES;

    float4 pf[NF4];
    auto prefetch = [&](int k) {
        const int j = rowOK ? __ldg(&nbr[(size_t)k * nOut + grow]) : nIn;
        if (j < nIn) {
            const float4* s = reinterpret_cast<const float4*>(in + (size_t)j * CIN) + part * NF4;
#pragma unroll
            for (int i = 0; i < NF4; ++i) pf[i] = s[i];
        } else {
#pragma unroll
            for (int i = 0; i < NF4; ++i) pf[i] = make_float4(0.f, 0.f, 0.f, 0.f);
        }
    };
    auto convert_sts = [&](uint32_t buf) {
#pragma unroll
        for (int i = 0; i < NF4; ++i) {
            const int kt = (KTILES == 4) ? (part * 2 + (i >> 2)) : part;
            const int regb = ((gr >> 3) & 1) | ((i & 2) ? 2 : 0);
            const int lane0 = ((gr & 7) << 2) + ((i & 1) << 1);
            const uint32_t w0 = (uint32_t)(((kt * 4 + regb) * 33 + lane0) * 4);
            const float4 x = pf[i];
            const uint32_t h0 = cvt2(x.x, x.y);
            const uint32_t h1 = cvt2(x.z, x.w);
            const float l0 = x.x - __uint_as_float(h0 << 16);
            const float l1 = x.y - __uint_as_float(h0 & 0xFFFF0000u);
            const float l2 = x.z - __uint_as_float(h1 << 16);
            const float l3 = x.w - __uint_as_float(h1 & 0xFFFF0000u);
            const uint32_t q0 = cvt2(l0, l1);
            const uint32_t q1 = cvt2(l2, l3);
            st32(buf + w0, h0);
            st32(buf + w0 + 4, h1);
            st32(buf + ATERM_BYTES + w0, q0);
            st32(buf + ATERM_BYTES + w0 + 4, q1);
        }
    };

    float acc[8][4];
#pragma unroll
    for (int nt = 0; nt < 8; ++nt)
#pragma unroll
        for (int j = 0; j < 4; ++j) acc[nt][j] = 0.f;

    prefetch(0);
    convert_sts(abuf0);
    __syncwarp();

    for (int k = 0; k < KTAPS; ++k) {
        const uint32_t cur = (k & 1) ? abuf1 : abuf0;
        const uint32_t nxt = (k & 1) ? abuf0 : abuf1;
        if (k + 1 < KTAPS) prefetch(k + 1);
        const uint32_t* wtap = Wg + (size_t)k * TAPW;
#pragma unroll
        for (int kt = 0; kt < KTILES; ++kt) {
            uint32_t ah[4], al[4];
#pragma unroll
            for (int j = 0; j < 4; ++j) {
                const uint32_t ao = (uint32_t)(((kt * 4 + j) * 33 + l) * 4);
                ah[j] = lds32(cur + ao);
                al[j] = lds32(cur + ATERM_BYTES + ao);
            }
#pragma unroll
            for (int nt = 0; nt < 8; ++nt) {
                const uint32_t widx = ((kt * 8 + nt) * 32 + l) * 2;
                const uint2 bhv = __ldg(reinterpret_cast<const uint2*>(wtap + widx));
                const uint2 blv = __ldg(reinterpret_cast<const uint2*>(wtap + LOW + widx));
                uint32_t bh[2] = {bhv.x, bhv.y};
                uint32_t bl[2] = {blv.x, blv.y};
                mma_bf16(acc[nt], ah, bh);
                mma_bf16(acc[nt], al, bh);
                mma_bf16(acc[nt], ah, bl);
            }
        }
        if (k + 1 < KTAPS) convert_sts(nxt);
        __syncwarp();
    }

    // ---- epilogue: write D fragments ----
    const int dg = l >> 2, dt = l & 3;
    const int row0 = rowBase + dg;
    const int row1 = rowBase + dg + 8;
    if (row0 < nOut) {
        float* o = out + (size_t)row0 * 64 + dt * 2;
#pragma unroll
        for (int nt = 0; nt < 8; ++nt)
            *reinterpret_cast<float2*>(o + nt * 8) = make_float2(acc[nt][0], acc[nt][1]);
    }
    if (row1 < nOut) {
        float* o = out + (size_t)row1 * 64 + dt * 2;
#pragma unroll
        for (int nt = 0; nt < 8; ++nt)
            *reinterpret_cast<float2*>(o + nt * 8) = make_float2(acc[nt][2], acc[nt][3]);
    }

    if (STATS) {
        // per-warp column sums via shfl over the dg lanes (invalid rows are 0)
#pragma unroll
        for (int nt = 0; nt < 8; ++nt) {
#pragma unroll
            for (int j = 0; j < 2; ++j) {
                float ss = acc[nt][j] + acc[nt][j + 2];
                float qq = acc[nt][j] * acc[nt][j] + acc[nt][j + 2] * acc[nt][j + 2];
                ss += __shfl_xor_sync(0xFFFFFFFFu, ss, 4);
                qq += __shfl_xor_sync(0xFFFFFFFFu, qq, 4);
                ss += __shfl_xor_sync(0xFFFFFFFFu, ss, 8);
                qq += __shfl_xor_sync(0xFFFFFFFFu, qq, 8);
                ss += __shfl_xor_sync(0xFFFFFFFFu, ss, 16);
                qq += __shfl_xor_sync(0xFFFFFFFFu, qq, 16);
                if (l < 4) {
                    redS[w][nt * 8 + l * 2 + j] = ss;
                    redQ[w][nt * 8 + l * 2 + j] = qq;
                }
            }
        }
        __syncthreads();
        if (t < 64) {
            float s = 0.f, q = 0.f;
#pragma unroll
            for (int ww = 0; ww < 8; ++ww) { s += redS[ww][t]; q += redQ[ww][t]; }
            pSum[(size_t)blockIdx.x * 64 + t] = s;
            pSq [(size_t)blockIdx.x * 64 + t] = q;
        }
        __syncthreads();
        __threadfence();
        if (t == 0) s_last = (atomicAdd(&g_tick, 1u) == gridDim.x - 1u) ? 1u : 0u;
        __syncthreads();
        if (s_last) {
            __threadfence();
            const int co = t & 63, sub = t >> 6;
            float s = 0.f, q = 0.f;
            for (int b = sub; b < (int)gridDim.x; b += 4) {
                s += pSum[(size_t)b * 64 + co];
                q += pSq[(size_t)b * 64 + co];
            }
            redS[sub][co] = s;
            redQ[sub][co] = q;
            __syncthreads();
            if (t < 64) {
                const float S = (redS[0][t] + redS[1][t]) + (redS[2][t] + redS[3][t]);
                const float Q = (redQ[0][t] + redQ[1][t]) + (redQ[2][t] + redQ[3][t]);
                const float inv = 1.0f / (float)nOut;
                const float m = S * inv;
                const float var = Q * inv - m * m;
                stOut[t] = m;
                stOut[64 + t] = rsqrtf(var + 1e-5f);
            }
            __syncthreads();
            if (t == 0) g_tick = 0u;
        }
    }
}

// ---------------------------------------------------------------------------
__global__ void bnact_kernel(float4* __restrict__ x, const float* __restrict__ st, long long n4)
{
    const long long i = (long long)blockIdx.x * blockDim.x + threadIdx.x;
    if (i >= n4) return;
    const int c = ((int)(i & 15)) * 4;
    float4 v = x[i];
    v.x = (v.x - st[c + 0]) * st[64 + c + 0];
    v.y = (v.y - st[c + 1]) * st[64 + c + 1];
    v.z = (v.z - st[c + 2]) * st[64 + c + 2];
    v.w = (v.w - st[c + 3]) * st[64 + c + 3];
    v.x = v.x > 0.f ? v.x : 0.01f * v.x;
    v.y = v.y > 0.f ? v.y : 0.01f * v.y;
    v.z = v.z > 0.f ? v.z : 0.01f * v.z;
    v.w = v.w > 0.f ? v.w : 0.01f * v.w;
    x[i] = v;
}

__global__ void combine_kernel(const float4* __restrict__ a, const float* __restrict__ sa,
                               const float4* __restrict__ b, const float* __restrict__ sb,
                               float4* __restrict__ o, long long n4)
{
    const long long i = (long long)blockIdx.x * blockDim.x + threadIdx.x;
    if (i >= n4) return;
    const int c = ((int)(i & 15)) * 4;
    float4 va = a[i];
    float4 vb = b[i];
    float4 r;
    float x;
    x = (va.x - sa[c + 0]) * sa[64 + c + 0]; x = x > 0.f ? x : 0.01f * x; r.x = x;
    x = (va.y - sa[c + 1]) * sa[64 + c + 1]; x = x > 0.f ? x : 0.01f * x; r.y = x;
    x = (va.z - sa[c + 2]) * sa[64 + c + 2]; x = x > 0.f ? x : 0.01f * x; r.z = x;
    x = (va.w - sa[c + 3]) * sa[64 + c + 3]; x = x > 0.f ? x : 0.01f * x; r.w = x;
    x = (vb.x - sb[c + 0]) * sb[64 + c + 0]; x = x > 0.f ? x : 0.01f * x; r.x += x;
    x = (vb.y - sb[c + 1]) * sb[64 + c + 1]; x = x > 0.f ? x : 0.01f * x; r.y += x;
    x = (vb.z - sb[c + 2]) * sb[64 + c + 2]; x = x > 0.f ? x : 0.01f * x; r.z += x;
    x = (vb.w - sb[c + 3]) * sb[64 + c + 3]; x = x > 0.f ? x : 0.01f * x; r.w += x;
    o[i] = r;
}

// out[m] = [x1 | x2 | x3] @ down_w  (fp32 FFMA2 path, warp-autonomous)
__global__ void __launch_bounds__(256)
final_kernel(const float* __restrict__ X1, const float* __restrict__ X2,
             const float* __restrict__ X3, const float* __restrict__ Wp,
             float* __restrict__ out, int M)
{
    __shared__ __align__(16) float buf[8][2][8][64];
    const int t = threadIdx.x;
    const int w = t >> 5;
    const int l = t & 31;
    const int rowBase = (blockIdx.x * 8 + w) * 8;
    const int gr = l >> 2;
    const int gp = l & 3;
    const int grow = rowBase + gr;
    const bool rowOK = (grow < M);

    const float* srcs[3] = {X1, X2, X3};
    auto prefetch = [&](int s, int b) {
        const float* src = srcs[s] + (size_t)(rowOK ? grow : 0) * 64;
        const int sz = rowOK ? 16 : 0;
        const uint32_t dbase = (uint32_t)__cvta_generic_to_shared(&buf[w][b][gr][0]);
#pragma unroll
        for (int i = 0; i < 4; ++i) {
            const int c4 = gp + 4 * i;
            asm volatile("cp.async.ca.shared.global [%0], [%1], 16, %2;\n"
                         :: "r"(dbase + c4 * 16), "l"(src + c4 * 4), "r"(sz));
        }
        asm volatile("cp.async.commit_group;\n");
    };

    u64 accA[8], accB[8];
#pragma unroll
    for (int r = 0; r < 8; ++r) { accA[r] = 0ull; accB[r] = 0ull; }

    prefetch(0, 0);
    for (int s = 0; s < 3; ++s) {
        if (s + 1 < 3) {
            prefetch(s + 1, (s + 1) & 1);
            asm volatile("cp.async.wait_group 1;\n");
        } else {
            asm volatile("cp.async.wait_group 0;\n");
        }
        __syncwarp();
        const float* wk = Wp + (size_t)s * (64 * 64);
        const float* frow = &buf[w][s & 1][0][0];
#pragma unroll
        for (int q = 0; q < 16; ++q) {
            const ulonglong2 wa = *reinterpret_cast<const ulonglong2*>(wk + (q * 64 + l) * 4);
            const ulonglong2 wb = *reinterpret_cast<const ulonglong2*>(wk + (q * 64 + l + 32) * 4);
#pragma unroll
            for (int r = 0; r < 8; ++r) {
                const ulonglong2 s2 =
                    *reinterpret_cast<const ulonglong2*>(frow + r * 64 + q * 4);
                accA[r] = ffma2(s2.x, wa.x, accA[r]);
                accA[r] = ffma2(s2.y, wa.y, accA[r]);
                accB[r] = ffma2(s2.x, wb.x, accB[r]);
                accB[r] = ffma2(s2.y, wb.y, accB[r]);
            }
        }
        __syncwarp();
    }
#pragma unroll
    for (int r = 0; r < 8; ++r) {
        const int orow = rowBase + r;
        if (orow < M) {
            out[(size_t)orow * 64 + l] =
                __uint_as_float((unsigned)accA[r]) + __uint_as_float((unsigned)(accA[r] >> 32));
            out[(size_t)orow * 64 + l + 32] =
                __uint_as_float((unsigned)accB[r]) + __uint_as_float((unsigned)(accB[r] >> 32));
        }
    }
}

// ---------------------------------------------------------------------------
extern "C" void kernel_launch(void* const* d_in, const int* in_sizes, int n_in,
                              void* d_out, int out_size)
{
    const float* feats  = (const float*)d_in[0];
    const float* down_w = (const float*)d_in[14];
    const int* n331_1 = (const int*)d_in[15];
    const int* n313_1 = (const int*)d_in[16];
    const int* pool_n = (const int*)d_in[17];
    const int* n331_2 = (const int*)d_in[18];
    const int* n313_2 = (const int*)d_in[19];
    const int* n331_3 = (const int*)d_in[20];
    const int* n313_3 = (const int*)d_in[21];

    const int N = in_sizes[0] / 32;
    const int M = out_size / 64;

    float *A, *B, *C, *X1, *X2, *X3, *pS, *pQ, *st, *Wt;
    uint32_t* Wb;
    cudaGetSymbolAddress((void**)&A,  g_A);
    cudaGetSymbolAddress((void**)&B,  g_B);
    cudaGetSymbolAddress((void**)&C,  g_C);
    cudaGetSymbolAddress((void**)&X1, g_X1);
    cudaGetSymbolAddress((void**)&X2, g_X2);
    cudaGetSymbolAddress((void**)&X3, g_X3);
    cudaGetSymbolAddress((void**)&pS, g_pS);
    cudaGetSymbolAddress((void**)&pQ, g_pQ);
    cudaGetSymbolAddress((void**)&st, g_st);
    cudaGetSymbolAddress((void**)&Wt, g_Wt);
    cudaGetSymbolAddress((void**)&Wb, g_Wb);
    float* st0 = st;
    float* st1 = st + 128;
    float* st2 = st + 256;
    float* st3 = st + 384;

    const size_t o0 = 0;
    const size_t o1 = 18432;
    const size_t o2 = 55296;
    const size_t o3 = 73728;
    const size_t o4 = 110592;
    const size_t o5 = 221184;
    const size_t o6 = 258048;
    const size_t o7 = 294912;
    const size_t o8 = 331776;
    const size_t o9 = 368640;
    const size_t o10 = 405504;
    const size_t o11 = 442368;
    const size_t o12 = 479232;

    // dynamic smem: A frag buffers only
    const int SM2 = 8 * 2 * (2 * 2 * 4 * 33 * 4);   // KTILES=2: 33792
    const int SM4 = 8 * 2 * (2 * 4 * 4 * 33 * 4);   // KTILES=4: 67584
    cudaFuncSetAttribute(mma_conv<2, 9, true>,   cudaFuncAttributeMaxDynamicSharedMemorySize, SM2);
    cudaFuncSetAttribute(mma_conv<4, 9, true>,   cudaFuncAttributeMaxDynamicSharedMemorySize, SM4);
    cudaFuncSetAttribute(mma_conv<4, 27, false>, cudaFuncAttributeMaxDynamicSharedMemorySize, SM4);

    WPtrs wp;
    for (int i = 0; i < 13; ++i) wp.p[i] = (const float*)d_in[1 + i];
    wprep<<<135, 256>>>(wp, Wb);
    wtrans_down<<<3, 256>>>(down_w, Wt);

    const int gN = (N + 127) / 128;
    const int gM = (M + 127) / 128;
    const long long n4N = (long long)N * 16;
    const long long n4M = (long long)M * 16;
    const int gbN = (int)((n4N + 255) / 256);
    const int gbM = (int)((n4M + 255) / 256);
    const int gMf = (M + 63) / 64;

    // ---- block 1 (N rows, 32 -> 64) ----
    mma_conv<2, 9, true><<<gN, 256, SM2>>>(feats, N, n331_1, N, Wb + o0, A, pS, pQ, st0);
    bnact_kernel<<<gbN, 256>>>((float4*)A, st0, n4N);
    mma_conv<4, 9, true><<<gN, 256, SM4>>>(A, N, n313_1, N, Wb + o1, B, pS, pQ, st1);
    mma_conv<2, 9, true><<<gN, 256, SM2>>>(feats, N, n313_1, N, Wb + o2, C, pS, pQ, st2);
    bnact_kernel<<<gbN, 256>>>((float4*)C, st2, n4N);
    mma_conv<4, 9, true><<<gN, 256, SM4>>>(C, N, n331_1, N, Wb + o3, A, pS, pQ, st3);
    combine_kernel<<<gbN, 256>>>((const float4*)A, st3, (const float4*)B, st1,
                                 (float4*)C, n4N);

    // ---- pool (K=27): C (N rows) -> X1 (M rows) ----
    mma_conv<4, 27, false><<<gM, 256, SM4>>>(C, N, pool_n, M, Wb + o4, X1, nullptr, nullptr, nullptr);

    // ---- block 2 (M rows, dilation 2) ----
    mma_conv<4, 9, true><<<gM, 256, SM4>>>(X1, M, n331_2, M, Wb + o5, A, pS, pQ, st0);
    bnact_kernel<<<gbM, 256>>>((float4*)A, st0, n4M);
    mma_conv<4, 9, true><<<gM, 256, SM4>>>(A, M, n313_2, M, Wb + o6, B, pS, pQ, st1);
    mma_conv<4, 9, true><<<gM, 256, SM4>>>(X1, M, n313_2, M, Wb + o7, C, pS, pQ, st2);
    bnact_kernel<<<gbM, 256>>>((float4*)C, st2, n4M);
    mma_conv<4, 9, true><<<gM, 256, SM4>>>(C, M, n331_2, M, Wb + o8, A, pS, pQ, st3);
    combine_kernel<<<gbM, 256>>>((const float4*)A, st3, (const float4*)B, st1,
                                 (float4*)X2, n4M);

    // ---- block 3 (M rows, dilation 3) ----
    mma_conv<4, 9, true><<<gM, 256, SM4>>>(X2, M, n331_3, M, Wb + o9, A, pS, pQ, st0);
    bnact_kernel<<<gbM, 256>>>((float4*)A, st0, n4M);
    mma_conv<4, 9, true><<<gM, 256, SM4>>>(A, M, n313_3, M, Wb + o10, B, pS, pQ, st1);
    mma_conv<4, 9, true><<<gM, 256, SM4>>>(X2, M, n313_3, M, Wb + o11, C, pS, pQ, st2);
    bnact_kernel<<<gbM, 256>>>((float4*)C, st2, n4M);
    mma_conv<4, 9, true><<<gM, 256, SM4>>>(C, M, n331_3, M, Wb + o12, A, pS, pQ, st3);
    combine_kernel<<<gbM, 256>>>((const float4*)A, st3, (const float4*)B, st1,
                                 (float4*)X3, n4M);

    // ---- final 1x1 fuse ----
    final_kernel<<<gMf, 256>>>(X1, X2, X3, Wt, (float*)d_out, M);
}